// round 4
// baseline (speedup 1.0000x reference)
#include <cuda_runtime.h>
#include <cuda_bf16.h>
#include <cstdint>
#include <math.h>

// x: [2,2048,1024], ctx: [2,2048,768], Wq: [1024,1024], Wkv: [768,2048], Wo: [1024,1024]
#define BATCH 2
#define SEQ_N 2048
#define SEQ_M 2048
#define CDIM 1024
#define CTXDIM 768
#define HEADS 16
#define DH 64

// ---------------- device scratch (allocation-free rule) ----------------
__device__ float g_Q [BATCH * SEQ_N * CDIM];
__device__ float g_KV[BATCH * SEQ_M * 2 * CDIM];
__device__ float g_AO[BATCH * SEQ_N * CDIM];
__device__ float g_WqT [CDIM * CDIM];
__device__ float g_WkvT[2 * CDIM * CTXDIM];
__device__ float g_WoT [CDIM * CDIM];

// ---------------- helpers ----------------
__device__ __forceinline__ float rna_tf32(float x) {
    float r;
    asm("cvt.rna.tf32.f32 %0, %1;" : "=f"(r) : "f"(x));
    return r;
}
__device__ __forceinline__ float exp2_fast(float x) {
    float r;
    asm("ex2.approx.ftz.f32 %0, %1;" : "=f"(r) : "f"(x));
    return r;
}
// D += A @ B  (m16n8k8, tf32 in, f32 acc)
__device__ __forceinline__ void mma_tf32(float* d, const uint32_t* a, const uint32_t* b) {
    asm volatile(
        "mma.sync.aligned.m16n8k8.row.col.f32.tf32.tf32.f32 "
        "{%0,%1,%2,%3}, {%4,%5,%6,%7}, {%8,%9}, {%0,%1,%2,%3};"
        : "+f"(d[0]), "+f"(d[1]), "+f"(d[2]), "+f"(d[3])
        : "r"(a[0]), "r"(a[1]), "r"(a[2]), "r"(a[3]), "r"(b[0]), "r"(b[1]));
}

// out[n][k] = rna(in[k][n]); in is [K,N] row-major
__global__ void transpose_rna_k(const float* __restrict__ in, float* __restrict__ out, int K, int N) {
    __shared__ float t[32][33];
    int n0 = blockIdx.x * 32, k0 = blockIdx.y * 32;
    int x = threadIdx.x, y = threadIdx.y;
#pragma unroll
    for (int i = 0; i < 32; i += 8)
        t[y + i][x] = in[(size_t)(k0 + y + i) * N + n0 + x];
    __syncthreads();
#pragma unroll
    for (int i = 0; i < 32; i += 8)
        out[(size_t)(n0 + y + i) * K + k0 + x] = rna_tf32(t[x][y + i]);
}

// ---------------- tf32 mma GEMM: C[M,N] = A[M,K] @ BT[N,K]^T ----------------
// 128x128 tile, BK=16, 256 threads (8 warps: 4 in M x 2 in N, warp = 32x64).
// RNA_A: round A elements (inputs not pre-rounded). RNA_OUT: round C output.
template <int RNA_A, int RNA_OUT>
__global__ __launch_bounds__(256) void gemm_mma(const float* __restrict__ A,
                                                const float* __restrict__ BT,
                                                float* __restrict__ C,
                                                int M, int N, int K)
{
    __shared__ float As[2][128 * 20];
    __shared__ float Bs[2][128 * 20];
    const int tid = threadIdx.x, lane = tid & 31, wid = tid >> 5;
    const int wm = (wid & 3) * 32, wn = (wid >> 2) * 64;
    const int bx = blockIdx.x * 128, by = blockIdx.y * 128;

    const float* Ag = A  + (size_t)by * K;
    const float* Bg = BT + (size_t)bx * K;

    float acc[2][8][4];
#pragma unroll
    for (int mi = 0; mi < 2; mi++)
#pragma unroll
        for (int j = 0; j < 8; j++)
#pragma unroll
            for (int q = 0; q < 4; q++) acc[mi][j][q] = 0.0f;

    float4 ra[2], rb[2];
#pragma unroll
    for (int i = 0; i < 2; i++) {
        int idx = tid + i * 256, r = idx >> 2, c = (idx & 3) * 4;
        ra[i] = *(const float4*)(Ag + (size_t)r * K + c);
        rb[i] = *(const float4*)(Bg + (size_t)r * K + c);
    }
#pragma unroll
    for (int i = 0; i < 2; i++) {
        int idx = tid + i * 256, r = idx >> 2, c = (idx & 3) * 4;
        if (RNA_A)
            ra[i] = make_float4(rna_tf32(ra[i].x), rna_tf32(ra[i].y),
                                rna_tf32(ra[i].z), rna_tf32(ra[i].w));
        *(float4*)&As[0][r * 20 + c] = ra[i];
        *(float4*)&Bs[0][r * 20 + c] = rb[i];
    }
    __syncthreads();

    const int nk = K >> 4;
    for (int kt = 0; kt < nk; kt++) {
        const int buf = kt & 1;
        if (kt + 1 < nk) {
            const float* Agn = Ag + (size_t)(kt + 1) * 16;
            const float* Bgn = Bg + (size_t)(kt + 1) * 16;
#pragma unroll
            for (int i = 0; i < 2; i++) {
                int idx = tid + i * 256, r = idx >> 2, c = (idx & 3) * 4;
                ra[i] = *(const float4*)(Agn + (size_t)r * K + c);
                rb[i] = *(const float4*)(Bgn + (size_t)r * K + c);
            }
        }
#pragma unroll
        for (int s = 0; s < 2; s++) {
            const int k0 = s * 8;
            uint32_t af[2][4], bf[8][2];
#pragma unroll
            for (int mi = 0; mi < 2; mi++) {
                int rr = wm + mi * 16 + (lane >> 2);
                af[mi][0] = __float_as_uint(As[buf][rr * 20 + k0 + (lane & 3)]);
                af[mi][1] = __float_as_uint(As[buf][(rr + 8) * 20 + k0 + (lane & 3)]);
                af[mi][2] = __float_as_uint(As[buf][rr * 20 + k0 + (lane & 3) + 4]);
                af[mi][3] = __float_as_uint(As[buf][(rr + 8) * 20 + k0 + (lane & 3) + 4]);
            }
#pragma unroll
            for (int j = 0; j < 8; j++) {
                int nb = wn + j * 8 + (lane >> 2);
                bf[j][0] = __float_as_uint(Bs[buf][nb * 20 + k0 + (lane & 3)]);
                bf[j][1] = __float_as_uint(Bs[buf][nb * 20 + k0 + (lane & 3) + 4]);
            }
#pragma unroll
            for (int mi = 0; mi < 2; mi++)
#pragma unroll
                for (int j = 0; j < 8; j++)
                    mma_tf32(acc[mi][j], af[mi], bf[j]);
        }
        if (kt + 1 < nk) {
            __syncthreads();
            const int nb2 = (kt + 1) & 1;
#pragma unroll
            for (int i = 0; i < 2; i++) {
                int idx = tid + i * 256, r = idx >> 2, c = (idx & 3) * 4;
                if (RNA_A)
                    ra[i] = make_float4(rna_tf32(ra[i].x), rna_tf32(ra[i].y),
                                        rna_tf32(ra[i].z), rna_tf32(ra[i].w));
                *(float4*)&As[nb2][r * 20 + c] = ra[i];
                *(float4*)&Bs[nb2][r * 20 + c] = rb[i];
            }
            __syncthreads();
        }
    }

#pragma unroll
    for (int mi = 0; mi < 2; mi++) {
        int r0 = by + wm + mi * 16 + (lane >> 2);
#pragma unroll
        for (int j = 0; j < 8; j++) {
            int col = bx + wn + j * 8 + 2 * (lane & 3);
            float2 v0, v1;
            if (RNA_OUT) {
                v0 = make_float2(rna_tf32(acc[mi][j][0]), rna_tf32(acc[mi][j][1]));
                v1 = make_float2(rna_tf32(acc[mi][j][2]), rna_tf32(acc[mi][j][3]));
            } else {
                v0 = make_float2(acc[mi][j][0], acc[mi][j][1]);
                v1 = make_float2(acc[mi][j][2], acc[mi][j][3]);
            }
            *(float2*)(C + (size_t)r0 * N + col)       = v0;
            *(float2*)(C + (size_t)(r0 + 8) * N + col) = v1;
        }
    }
}

// ---------------- FlashAttention-2 with tf32 mma ----------------
// Grid (B*H=32, N/128=16), 256 threads (8 warps; warp = 16 query rows).
// Smem floats: Qs[128][68], Ks[64][68], Vs[64][72], Ps[8][16][68] ~= 103 KB.
static constexpr int QS_OFF = 0;
static constexpr int KS_OFF = 128 * 68;
static constexpr int VS_OFF = KS_OFF + 64 * 68;
static constexpr int PS_OFF = VS_OFF + 64 * 72;
static constexpr int ATTN_SMEM = (PS_OFF + 8 * 16 * 68) * 4;  // bytes

__global__ __launch_bounds__(256) void attn_mma(const float* __restrict__ Q,
                                                const float* __restrict__ KV,
                                                float* __restrict__ O)
{
    extern __shared__ float smf[];
    float* Qs = smf + QS_OFF;
    float* Ks = smf + KS_OFF;
    float* Vs = smf + VS_OFF;

    const int tid = threadIdx.x, lane = tid & 31, wid = tid >> 5;
    const int b = blockIdx.x >> 4, h = blockIdx.x & 15;
    const int n0 = blockIdx.y * 128;

    const float* Qg = Q  + ((size_t)(b * SEQ_N + n0)) * CDIM + h * DH;
    const float* Kg = KV + (size_t)b * SEQ_M * (2 * CDIM) + h * DH;
    const float* Vg = Kg + CDIM;

    float* Pw = smf + PS_OFF + wid * (16 * 68);

    // load Q tile (128 x 64)
#pragma unroll
    for (int i = 0; i < 8; i++) {
        int idx = tid + i * 256, r = idx >> 4, c = (idx & 15) * 4;
        *(float4*)&Qs[r * 68 + c] = *(const float4*)(Qg + (size_t)r * CDIM + c);
    }

    const float SCALE = 0.125f * 1.4426950408889634f;  // Dh^-0.5 * log2(e)
    float m0r = -1e30f, m1r = -1e30f, l0 = 0.0f, l1 = 0.0f;
    float oacc[8][4];
#pragma unroll
    for (int j = 0; j < 8; j++)
#pragma unroll
        for (int q = 0; q < 4; q++) oacc[j][q] = 0.0f;

    const int r_ = lane >> 2, kq = lane & 3;

    for (int mt = 0; mt < SEQ_M; mt += 64) {
        __syncthreads();  // previous S/PV done with Ks/Vs (and Q stores before 1st mma)
#pragma unroll
        for (int i = 0; i < 4; i++) {
            int idx = tid + i * 256, r = idx >> 4, c = (idx & 15) * 4;
            *(float4*)&Ks[r * 68 + c] = *(const float4*)(Kg + (size_t)(mt + r) * (2 * CDIM) + c);
            *(float4*)&Vs[r * 72 + c] = *(const float4*)(Vg + (size_t)(mt + r) * (2 * CDIM) + c);
        }
        __syncthreads();

        // S = Q @ K^T  (warp: 16 x 64)
        float sacc[8][4];
#pragma unroll
        for (int j = 0; j < 8; j++)
#pragma unroll
            for (int q = 0; q < 4; q++) sacc[j][q] = 0.0f;

#pragma unroll
        for (int s = 0; s < 8; s++) {
            const int k0 = s * 8;
            uint32_t af[4];
            int rr = wid * 16 + r_;
            af[0] = __float_as_uint(Qs[rr * 68 + k0 + kq]);
            af[1] = __float_as_uint(Qs[(rr + 8) * 68 + k0 + kq]);
            af[2] = __float_as_uint(Qs[rr * 68 + k0 + kq + 4]);
            af[3] = __float_as_uint(Qs[(rr + 8) * 68 + k0 + kq + 4]);
#pragma unroll
            for (int j = 0; j < 8; j++) {
                uint32_t bf[2];
                int nb = j * 8 + r_;
                bf[0] = __float_as_uint(Ks[nb * 68 + k0 + kq]);
                bf[1] = __float_as_uint(Ks[nb * 68 + k0 + kq + 4]);
                mma_tf32(sacc[j], af, bf);
            }
        }

        // online softmax (exp2 domain); thread owns rows r_ and r_+8 of warp tile
        float rm0 = -1e30f, rm1 = -1e30f;
#pragma unroll
        for (int j = 0; j < 8; j++) {
            rm0 = fmaxf(rm0, fmaxf(sacc[j][0], sacc[j][1]));
            rm1 = fmaxf(rm1, fmaxf(sacc[j][2], sacc[j][3]));
        }
        rm0 = fmaxf(rm0, __shfl_xor_sync(0xffffffffu, rm0, 1));
        rm0 = fmaxf(rm0, __shfl_xor_sync(0xffffffffu, rm0, 2));
        rm1 = fmaxf(rm1, __shfl_xor_sync(0xffffffffu, rm1, 1));
        rm1 = fmaxf(rm1, __shfl_xor_sync(0xffffffffu, rm1, 2));
        rm0 *= SCALE; rm1 *= SCALE;
        float mn0 = fmaxf(m0r, rm0), mn1 = fmaxf(m1r, rm1);
        float c0 = exp2_fast(m0r - mn0), c1 = exp2_fast(m1r - mn1);
        m0r = mn0; m1r = mn1;

        float rs0 = 0.0f, rs1 = 0.0f;
#pragma unroll
        for (int j = 0; j < 8; j++) {
            float p00 = rna_tf32(exp2_fast(fmaf(sacc[j][0], SCALE, -mn0)));
            float p01 = rna_tf32(exp2_fast(fmaf(sacc[j][1], SCALE, -mn0)));
            float p10 = rna_tf32(exp2_fast(fmaf(sacc[j][2], SCALE, -mn1)));
            float p11 = rna_tf32(exp2_fast(fmaf(sacc[j][3], SCALE, -mn1)));
            rs0 += p00 + p01;
            rs1 += p10 + p11;
            int col = j * 8 + 2 * kq;
            Pw[r_ * 68 + col]           = p00;
            Pw[r_ * 68 + col + 1]       = p01;
            Pw[(r_ + 8) * 68 + col]     = p10;
            Pw[(r_ + 8) * 68 + col + 1] = p11;
        }
        rs0 += __shfl_xor_sync(0xffffffffu, rs0, 1);
        rs0 += __shfl_xor_sync(0xffffffffu, rs0, 2);
        rs1 += __shfl_xor_sync(0xffffffffu, rs1, 1);
        rs1 += __shfl_xor_sync(0xffffffffu, rs1, 2);
        l0 = l0 * c0 + rs0;
        l1 = l1 * c1 + rs1;
#pragma unroll
        for (int j = 0; j < 8; j++) {
            oacc[j][0] *= c0; oacc[j][1] *= c0;
            oacc[j][2] *= c1; oacc[j][3] *= c1;
        }
        __syncwarp();

        // O += P @ V  (A = Pw from smem, B = Vs)
#pragma unroll
        for (int s = 0; s < 8; s++) {
            const int k0 = s * 8;
            uint32_t af[4];
            af[0] = __float_as_uint(Pw[r_ * 68 + k0 + kq]);
            af[1] = __float_as_uint(Pw[(r_ + 8) * 68 + k0 + kq]);
            af[2] = __float_as_uint(Pw[r_ * 68 + k0 + kq + 4]);
            af[3] = __float_as_uint(Pw[(r_ + 8) * 68 + k0 + kq + 4]);
#pragma unroll
            for (int j = 0; j < 8; j++) {
                uint32_t bf[2];
                bf[0] = __float_as_uint(Vs[(k0 + kq) * 72 + j * 8 + r_]);
                bf[1] = __float_as_uint(Vs[(k0 + kq + 4) * 72 + j * 8 + r_]);
                mma_tf32(oacc[j], af, bf);
            }
        }
    }

    // epilogue: normalize, rna-round, store
    float inv0 = 1.0f / l0, inv1 = 1.0f / l1;
    int row = n0 + wid * 16 + r_;
    float* Ob = O + ((size_t)(b * SEQ_N + row)) * CDIM + h * DH;
#pragma unroll
    for (int j = 0; j < 8; j++) {
        int col = j * 8 + 2 * kq;
        *(float2*)(Ob + col) =
            make_float2(rna_tf32(oacc[j][0] * inv0), rna_tf32(oacc[j][1] * inv0));
        *(float2*)(Ob + (size_t)8 * CDIM + col) =
            make_float2(rna_tf32(oacc[j][2] * inv1), rna_tf32(oacc[j][3] * inv1));
    }
}

// ---------------------------------------------------------------------------
extern "C" void kernel_launch(void* const* d_in, const int* in_sizes, int n_in,
                              void* d_out, int out_size)
{
    const float* x   = (const float*)d_in[0];
    const float* ctx = (const float*)d_in[1];
    const float* Wq  = (const float*)d_in[2];
    const float* Wkv = (const float*)d_in[3];
    const float* Wo  = (const float*)d_in[4];
    float* out = (float*)d_out;

    float *Qb, *KVb, *AOb, *WqT, *WkvT, *WoT;
    cudaGetSymbolAddress((void**)&Qb,   g_Q);
    cudaGetSymbolAddress((void**)&KVb,  g_KV);
    cudaGetSymbolAddress((void**)&AOb,  g_AO);
    cudaGetSymbolAddress((void**)&WqT,  g_WqT);
    cudaGetSymbolAddress((void**)&WkvT, g_WkvT);
    cudaGetSymbolAddress((void**)&WoT,  g_WoT);

    // weight transposes to [N,K] with tf32 rounding
    transpose_rna_k<<<dim3(CDIM / 32, CDIM / 32), dim3(32, 8)>>>(Wq, WqT, CDIM, CDIM);
    transpose_rna_k<<<dim3(2 * CDIM / 32, CTXDIM / 32), dim3(32, 8)>>>(Wkv, WkvT, CTXDIM, 2 * CDIM);
    transpose_rna_k<<<dim3(CDIM / 32, CDIM / 32), dim3(32, 8)>>>(Wo, WoT, CDIM, CDIM);

    // Q = x @ Wq (A rounded in-kernel; output rounded: S-mma operand)
    gemm_mma<1, 1><<<dim3(CDIM / 128, BATCH * SEQ_N / 128), 256>>>(
        x, WqT, Qb, BATCH * SEQ_N, CDIM, CDIM);
    // KV = ctx @ Wkv (A rounded in-kernel; output rounded: K,V are mma operands)
    gemm_mma<1, 1><<<dim3(2 * CDIM / 128, BATCH * SEQ_M / 128), 256>>>(
        ctx, WkvT, KVb, BATCH * SEQ_M, 2 * CDIM, CTXDIM);

    // fused flash attention (tf32 mma); output already rna-rounded
    cudaFuncSetAttribute(attn_mma, cudaFuncAttributeMaxDynamicSharedMemorySize, ATTN_SMEM);
    attn_mma<<<dim3(BATCH * HEADS, SEQ_N / 128), 256, ATTN_SMEM>>>(Qb, KVb, AOb);

    // out = AO @ Wo (AO pre-rounded, no extra rounding)
    gemm_mma<0, 0><<<dim3(CDIM / 128, BATCH * SEQ_N / 128), 256>>>(
        AOb, WoT, out, BATCH * SEQ_N, CDIM, CDIM);
}

// round 5
// speedup vs baseline: 1.3924x; 1.3924x over previous
#include <cuda_runtime.h>
#include <cuda_bf16.h>
#include <cstdint>
#include <math.h>

// x: [2,2048,1024], ctx: [2,2048,768], Wq: [1024,1024], Wkv: [768,2048], Wo: [1024,1024]
#define BATCH 2
#define SEQ_N 2048
#define SEQ_M 2048
#define CDIM 1024
#define CTXDIM 768
#define HEADS 16
#define DH 64

// ---------------- device scratch (allocation-free rule) ----------------
__device__ float g_Q [BATCH * SEQ_N * CDIM];
__device__ float g_KV[BATCH * SEQ_M * 2 * CDIM];
__device__ float g_AO[BATCH * SEQ_N * CDIM];
__device__ float g_WqT [CDIM * CDIM];
__device__ float g_WkvT[2 * CDIM * CTXDIM];
__device__ float g_WoT [CDIM * CDIM];

// ---------------- helpers ----------------
__device__ __forceinline__ float rna_tf32(float x) {
    float r;
    asm("cvt.rna.tf32.f32 %0, %1;" : "=f"(r) : "f"(x));
    return r;
}
__device__ __forceinline__ float exp2_fast(float x) {
    float r;
    asm("ex2.approx.ftz.f32 %0, %1;" : "=f"(r) : "f"(x));
    return r;
}
// D += A @ B  (m16n8k8, tf32 in, f32 acc)
__device__ __forceinline__ void mma_tf32(float* d, const uint32_t* a, const uint32_t* b) {
    asm volatile(
        "mma.sync.aligned.m16n8k8.row.col.f32.tf32.tf32.f32 "
        "{%0,%1,%2,%3}, {%4,%5,%6,%7}, {%8,%9}, {%0,%1,%2,%3};"
        : "+f"(d[0]), "+f"(d[1]), "+f"(d[2]), "+f"(d[3])
        : "r"(a[0]), "r"(a[1]), "r"(a[2]), "r"(a[3]), "r"(b[0]), "r"(b[1]));
}

// out[n][k] = rna(in[k][n]); in is [K,N] row-major
__global__ void transpose_rna_k(const float* __restrict__ in, float* __restrict__ out, int K, int N) {
    __shared__ float t[32][33];
    int n0 = blockIdx.x * 32, k0 = blockIdx.y * 32;
    int x = threadIdx.x, y = threadIdx.y;
#pragma unroll
    for (int i = 0; i < 32; i += 8)
        t[y + i][x] = in[(size_t)(k0 + y + i) * N + n0 + x];
    __syncthreads();
#pragma unroll
    for (int i = 0; i < 32; i += 8)
        out[(size_t)(n0 + y + i) * K + k0 + x] = rna_tf32(t[x][y + i]);
}

// ---------------- tf32 mma GEMM: C[M,N] = A[M,K] @ BT[N,K]^T ----------------
// 128x128 tile, BK=16, 256 threads (8 warps: 4 in M x 2 in N; warp = 32x64).
// Smem holds FRAGMENT-MAJOR permuted tiles:
//  A: float4 group idx = s*256 + t16*32 + r_*4 + (kq ^ (r_&3));  (s=k/8, t16=row/16, r_=row&7, kq=k&3)
//     group slots: v = ((row>>3)&1) | (((k>>2)&1)<<1)   -> af[0..3] order for LDS.128
//  B: float2 group idx = s*512 + n*4 + (kq ^ (n&3)); slot v = (k>>2)&1 -> bf[0..1] for LDS.64
template <int RNA_A, int RNA_OUT>
__global__ __launch_bounds__(256) void gemm_mma(const float* __restrict__ A,
                                                const float* __restrict__ BT,
                                                float* __restrict__ C,
                                                int M, int N, int K)
{
    __shared__ float Ap[2][2048];   // 8 KB per buffer
    __shared__ float Bp[2][2048];
    const int tid = threadIdx.x, lane = tid & 31, wid = tid >> 5;
    const int wm4 = (wid & 3), wn = (wid >> 2) * 64;
    const int bx = blockIdx.x * 128, by = blockIdx.y * 128;
    const int r_ = lane >> 2, kq = lane & 3;
    const int kqs = kq ^ (r_ & 3);

    const float* Ag = A  + (size_t)by * K;
    const float* Bg = BT + (size_t)bx * K;

    float acc[2][8][4];
#pragma unroll
    for (int mi = 0; mi < 2; mi++)
#pragma unroll
        for (int j = 0; j < 8; j++)
#pragma unroll
            for (int q = 0; q < 4; q++) acc[mi][j][q] = 0.0f;

    // per-thread global-load coords: row r = idx>>2, k-cols c..c+3, c = (idx&3)*4
    float4 ra[2], rb[2];

    // permuted smem store of one loaded float4 (row r, cols c..c+3)
    auto storeA = [&](int buf, int r, int c, float4 v) {
        float vv[4] = {v.x, v.y, v.z, v.w};
        int t16 = r >> 4, rl = r & 7, rbit = (r >> 3) & 1;
#pragma unroll
        for (int e = 0; e < 4; e++) {
            int k = c + e;
            int s = k >> 3, kk = (k & 3) ^ (rl & 3);
            int vslot = rbit | (((k >> 2) & 1) << 1);
            float val = RNA_A ? rna_tf32(vv[e]) : vv[e];
            Ap[buf][(s * 256 + t16 * 32 + rl * 4 + kk) * 4 + vslot] = val;
        }
    };
    auto storeB = [&](int buf, int n, int c, float4 v) {
        float vv[4] = {v.x, v.y, v.z, v.w};
#pragma unroll
        for (int e = 0; e < 4; e++) {
            int k = c + e;
            int s = k >> 3, kk = (k & 3) ^ (n & 3);
            int vslot = (k >> 2) & 1;
            Bp[buf][(s * 512 + n * 4 + kk) * 2 + vslot] = vv[e];
        }
    };

#pragma unroll
    for (int i = 0; i < 2; i++) {
        int idx = tid + i * 256, r = idx >> 2, c = (idx & 3) * 4;
        ra[i] = *(const float4*)(Ag + (size_t)r * K + c);
        rb[i] = *(const float4*)(Bg + (size_t)r * K + c);
    }
#pragma unroll
    for (int i = 0; i < 2; i++) {
        int idx = tid + i * 256, r = idx >> 2, c = (idx & 3) * 4;
        storeA(0, r, c, ra[i]);
        storeB(0, r, c, rb[i]);
    }
    __syncthreads();

    const int nk = K >> 4;
    for (int kt = 0; kt < nk; kt++) {
        const int buf = kt & 1;
        if (kt + 1 < nk) {
            const float* Agn = Ag + (size_t)(kt + 1) * 16;
            const float* Bgn = Bg + (size_t)(kt + 1) * 16;
#pragma unroll
            for (int i = 0; i < 2; i++) {
                int idx = tid + i * 256, r = idx >> 2, c = (idx & 3) * 4;
                ra[i] = *(const float4*)(Agn + (size_t)r * K + c);
                rb[i] = *(const float4*)(Bgn + (size_t)r * K + c);
            }
        }
#pragma unroll
        for (int s = 0; s < 2; s++) {
            uint32_t af[2][4], bf[8][2];
#pragma unroll
            for (int mi = 0; mi < 2; mi++) {
                int t16 = wm4 * 2 + mi;
                int fa = s * 256 + t16 * 32 + r_ * 4 + kqs;
                float4 v = *(const float4*)&Ap[buf][fa * 4];
                af[mi][0] = __float_as_uint(v.x);
                af[mi][1] = __float_as_uint(v.y);
                af[mi][2] = __float_as_uint(v.z);
                af[mi][3] = __float_as_uint(v.w);
            }
#pragma unroll
            for (int j = 0; j < 8; j++) {
                int nb = wn + j * 8 + r_;
                int fb = s * 512 + nb * 4 + kqs;   // nb&3 == r_&3
                float2 v = *(const float2*)&Bp[buf][fb * 2];
                bf[j][0] = __float_as_uint(v.x);
                bf[j][1] = __float_as_uint(v.y);
            }
#pragma unroll
            for (int mi = 0; mi < 2; mi++)
#pragma unroll
                for (int j = 0; j < 8; j++)
                    mma_tf32(acc[mi][j], af[mi], bf[j]);
        }
        if (kt + 1 < nk) {
            __syncthreads();
            const int nb2 = (kt + 1) & 1;
#pragma unroll
            for (int i = 0; i < 2; i++) {
                int idx = tid + i * 256, r = idx >> 2, c = (idx & 3) * 4;
                storeA(nb2, r, c, ra[i]);
                storeB(nb2, r, c, rb[i]);
            }
            __syncthreads();
        }
    }

#pragma unroll
    for (int mi = 0; mi < 2; mi++) {
        int r0 = by + wm4 * 32 + mi * 16 + r_;
#pragma unroll
        for (int j = 0; j < 8; j++) {
            int col = bx + wn + j * 8 + 2 * kq;
            float2 v0, v1;
            if (RNA_OUT) {
                v0 = make_float2(rna_tf32(acc[mi][j][0]), rna_tf32(acc[mi][j][1]));
                v1 = make_float2(rna_tf32(acc[mi][j][2]), rna_tf32(acc[mi][j][3]));
            } else {
                v0 = make_float2(acc[mi][j][0], acc[mi][j][1]);
                v1 = make_float2(acc[mi][j][2], acc[mi][j][3]);
            }
            *(float2*)(C + (size_t)r0 * N + col)       = v0;
            *(float2*)(C + (size_t)(r0 + 8) * N + col) = v1;
        }
    }
}

// ---------------- FlashAttention-2 with tf32 mma (R3 config) ----------------
// Grid (B*H=32, N/64=32), 128 threads (4 warps; warp = 16 query rows).
static constexpr int QS_OFF = 0;
static constexpr int KS_OFF = 64 * 68;
static constexpr int VS_OFF = 2 * 64 * 68;
static constexpr int PS_OFF = 2 * 64 * 68 + 64 * 72;
static constexpr int ATTN_SMEM = (PS_OFF + 4 * 16 * 68) * 4;  // bytes

__global__ __launch_bounds__(128) void attn_mma(const float* __restrict__ Q,
                                                const float* __restrict__ KV,
                                                float* __restrict__ O)
{
    extern __shared__ float smf[];
    float* Qs = smf + QS_OFF;
    float* Ks = smf + KS_OFF;
    float* Vs = smf + VS_OFF;

    const int tid = threadIdx.x, lane = tid & 31, wid = tid >> 5;
    const int b = blockIdx.x >> 4, h = blockIdx.x & 15;
    const int n0 = blockIdx.y * 64;

    const float* Qg = Q  + ((size_t)(b * SEQ_N + n0)) * CDIM + h * DH;
    const float* Kg = KV + (size_t)b * SEQ_M * (2 * CDIM) + h * DH;
    const float* Vg = Kg + CDIM;

    float* Pw = smf + PS_OFF + wid * (16 * 68);

#pragma unroll
    for (int i = 0; i < 8; i++) {
        int idx = tid + i * 128, r = idx >> 4, c = (idx & 15) * 4;
        *(float4*)&Qs[r * 68 + c] = *(const float4*)(Qg + (size_t)r * CDIM + c);
    }

    const float SCALE = 0.125f * 1.4426950408889634f;
    float m0r = -1e30f, m1r = -1e30f, l0 = 0.0f, l1 = 0.0f;
    float oacc[8][4];
#pragma unroll
    for (int j = 0; j < 8; j++)
#pragma unroll
        for (int q = 0; q < 4; q++) oacc[j][q] = 0.0f;

    const int r_ = lane >> 2, kq = lane & 3;

    for (int mt = 0; mt < SEQ_M; mt += 64) {
        __syncthreads();
#pragma unroll
        for (int i = 0; i < 8; i++) {
            int idx = tid + i * 128, r = idx >> 4, c = (idx & 15) * 4;
            *(float4*)&Ks[r * 68 + c] = *(const float4*)(Kg + (size_t)(mt + r) * (2 * CDIM) + c);
            *(float4*)&Vs[r * 72 + c] = *(const float4*)(Vg + (size_t)(mt + r) * (2 * CDIM) + c);
        }
        __syncthreads();

        float sacc[8][4];
#pragma unroll
        for (int j = 0; j < 8; j++)
#pragma unroll
            for (int q = 0; q < 4; q++) sacc[j][q] = 0.0f;

#pragma unroll
        for (int s = 0; s < 8; s++) {
            const int k0 = s * 8;
            uint32_t af[4];
            int rr = wid * 16 + r_;
            af[0] = __float_as_uint(Qs[rr * 68 + k0 + kq]);
            af[1] = __float_as_uint(Qs[(rr + 8) * 68 + k0 + kq]);
            af[2] = __float_as_uint(Qs[rr * 68 + k0 + kq + 4]);
            af[3] = __float_as_uint(Qs[(rr + 8) * 68 + k0 + kq + 4]);
#pragma unroll
            for (int j = 0; j < 8; j++) {
                uint32_t bf[2];
                int nb = j * 8 + r_;
                bf[0] = __float_as_uint(Ks[nb * 68 + k0 + kq]);
                bf[1] = __float_as_uint(Ks[nb * 68 + k0 + kq + 4]);
                mma_tf32(sacc[j], af, bf);
            }
        }

        float rm0 = -1e30f, rm1 = -1e30f;
#pragma unroll
        for (int j = 0; j < 8; j++) {
            rm0 = fmaxf(rm0, fmaxf(sacc[j][0], sacc[j][1]));
            rm1 = fmaxf(rm1, fmaxf(sacc[j][2], sacc[j][3]));
        }
        rm0 = fmaxf(rm0, __shfl_xor_sync(0xffffffffu, rm0, 1));
        rm0 = fmaxf(rm0, __shfl_xor_sync(0xffffffffu, rm0, 2));
        rm1 = fmaxf(rm1, __shfl_xor_sync(0xffffffffu, rm1, 1));
        rm1 = fmaxf(rm1, __shfl_xor_sync(0xffffffffu, rm1, 2));
        rm0 *= SCALE; rm1 *= SCALE;
        float mn0 = fmaxf(m0r, rm0), mn1 = fmaxf(m1r, rm1);
        float c0 = exp2_fast(m0r - mn0), c1 = exp2_fast(m1r - mn1);
        m0r = mn0; m1r = mn1;

        float rs0 = 0.0f, rs1 = 0.0f;
#pragma unroll
        for (int j = 0; j < 8; j++) {
            float p00 = rna_tf32(exp2_fast(fmaf(sacc[j][0], SCALE, -mn0)));
            float p01 = rna_tf32(exp2_fast(fmaf(sacc[j][1], SCALE, -mn0)));
            float p10 = rna_tf32(exp2_fast(fmaf(sacc[j][2], SCALE, -mn1)));
            float p11 = rna_tf32(exp2_fast(fmaf(sacc[j][3], SCALE, -mn1)));
            rs0 += p00 + p01;
            rs1 += p10 + p11;
            int col = j * 8 + 2 * kq;
            Pw[r_ * 68 + col]           = p00;
            Pw[r_ * 68 + col + 1]       = p01;
            Pw[(r_ + 8) * 68 + col]     = p10;
            Pw[(r_ + 8) * 68 + col + 1] = p11;
        }
        rs0 += __shfl_xor_sync(0xffffffffu, rs0, 1);
        rs0 += __shfl_xor_sync(0xffffffffu, rs0, 2);
        rs1 += __shfl_xor_sync(0xffffffffu, rs1, 1);
        rs1 += __shfl_xor_sync(0xffffffffu, rs1, 2);
        l0 = l0 * c0 + rs0;
        l1 = l1 * c1 + rs1;
#pragma unroll
        for (int j = 0; j < 8; j++) {
            oacc[j][0] *= c0; oacc[j][1] *= c0;
            oacc[j][2] *= c1; oacc[j][3] *= c1;
        }
        __syncwarp();

#pragma unroll
        for (int s = 0; s < 8; s++) {
            const int k0 = s * 8;
            uint32_t af[4];
            af[0] = __float_as_uint(Pw[r_ * 68 + k0 + kq]);
            af[1] = __float_as_uint(Pw[(r_ + 8) * 68 + k0 + kq]);
            af[2] = __float_as_uint(Pw[r_ * 68 + k0 + kq + 4]);
            af[3] = __float_as_uint(Pw[(r_ + 8) * 68 + k0 + kq + 4]);
#pragma unroll
            for (int j = 0; j < 8; j++) {
                uint32_t bf[2];
                bf[0] = __float_as_uint(Vs[(k0 + kq) * 72 + j * 8 + r_]);
                bf[1] = __float_as_uint(Vs[(k0 + kq + 4) * 72 + j * 8 + r_]);
                mma_tf32(oacc[j], af, bf);
            }
        }
    }

    float inv0 = 1.0f / l0, inv1 = 1.0f / l1;
    int row = n0 + wid * 16 + r_;
    float* Ob = O + ((size_t)(b * SEQ_N + row)) * CDIM + h * DH;
#pragma unroll
    for (int j = 0; j < 8; j++) {
        int col = j * 8 + 2 * kq;
        *(float2*)(Ob + col) =
            make_float2(rna_tf32(oacc[j][0] * inv0), rna_tf32(oacc[j][1] * inv0));
        *(float2*)(Ob + (size_t)8 * CDIM + col) =
            make_float2(rna_tf32(oacc[j][2] * inv1), rna_tf32(oacc[j][3] * inv1));
    }
}

// ---------------------------------------------------------------------------
extern "C" void kernel_launch(void* const* d_in, const int* in_sizes, int n_in,
                              void* d_out, int out_size)
{
    const float* x   = (const float*)d_in[0];
    const float* ctx = (const float*)d_in[1];
    const float* Wq  = (const float*)d_in[2];
    const float* Wkv = (const float*)d_in[3];
    const float* Wo  = (const float*)d_in[4];
    float* out = (float*)d_out;

    float *Qb, *KVb, *AOb, *WqT, *WkvT, *WoT;
    cudaGetSymbolAddress((void**)&Qb,   g_Q);
    cudaGetSymbolAddress((void**)&KVb,  g_KV);
    cudaGetSymbolAddress((void**)&AOb,  g_AO);
    cudaGetSymbolAddress((void**)&WqT,  g_WqT);
    cudaGetSymbolAddress((void**)&WkvT, g_WkvT);
    cudaGetSymbolAddress((void**)&WoT,  g_WoT);

    // weight transposes to [N,K] with tf32 rounding
    transpose_rna_k<<<dim3(CDIM / 32, CDIM / 32), dim3(32, 8)>>>(Wq, WqT, CDIM, CDIM);
    transpose_rna_k<<<dim3(2 * CDIM / 32, CTXDIM / 32), dim3(32, 8)>>>(Wkv, WkvT, CTXDIM, 2 * CDIM);
    transpose_rna_k<<<dim3(CDIM / 32, CDIM / 32), dim3(32, 8)>>>(Wo, WoT, CDIM, CDIM);

    // Q = x @ Wq  (round A on smem store; round output: attention mma operand)
    gemm_mma<1, 1><<<dim3(CDIM / 128, BATCH * SEQ_N / 128), 256>>>(
        x, WqT, Qb, BATCH * SEQ_N, CDIM, CDIM);
    // KV = ctx @ Wkv
    gemm_mma<1, 1><<<dim3(2 * CDIM / 128, BATCH * SEQ_M / 128), 256>>>(
        ctx, WkvT, KVb, BATCH * SEQ_M, 2 * CDIM, CTXDIM);

    // fused flash attention (R3 config); output rna-rounded in epilogue
    cudaFuncSetAttribute(attn_mma, cudaFuncAttributeMaxDynamicSharedMemorySize, ATTN_SMEM);
    attn_mma<<<dim3(BATCH * HEADS, SEQ_N / 64), 128, ATTN_SMEM>>>(Qb, KVb, AOb);

    // out = AO @ Wo (AO pre-rounded; plain fp32 output)
    gemm_mma<0, 0><<<dim3(CDIM / 128, BATCH * SEQ_N / 128), 256>>>(
        AOb, WoT, out, BATCH * SEQ_N, CDIM, CDIM);
}

// round 6
// speedup vs baseline: 3.0831x; 2.2143x over previous
#include <cuda_runtime.h>
#include <cuda_fp16.h>
#include <cstdint>

// x: [2,2048,1024], ctx: [2,2048,768], Wq: [1024,1024], Wkv: [768,2048], Wo: [1024,1024]
#define BATCH 2
#define SEQ_N 2048
#define SEQ_M 2048
#define CDIM 1024
#define CTXDIM 768
#define HEADS 16
#define DH 64

// ---------------- device scratch (allocation-free rule) ----------------
__device__ __half g_xh [BATCH * SEQ_N * CDIM];
__device__ __half g_ch [BATCH * SEQ_M * CTXDIM];
__device__ __half g_Qh [BATCH * SEQ_N * CDIM];
__device__ __half g_KVh[BATCH * SEQ_M * 2 * CDIM];
__device__ __half g_Vt [BATCH * HEADS * DH * SEQ_M];
__device__ __half g_AOh[BATCH * SEQ_N * CDIM];
__device__ __half g_WqTh [CDIM * CDIM];
__device__ __half g_WkvTh[2 * CDIM * CTXDIM];
__device__ __half g_WoTh [CDIM * CDIM];

// ---------------- helpers ----------------
__device__ __forceinline__ uint32_t smem_u32(const void* p) {
    uint32_t a;
    asm("{ .reg .u64 t; cvta.to.shared.u64 t, %1; cvt.u32.u64 %0, t; }" : "=r"(a) : "l"(p));
    return a;
}
__device__ __forceinline__ float exp2_fast(float x) {
    float r;
    asm("ex2.approx.ftz.f32 %0, %1;" : "=f"(r) : "f"(x));
    return r;
}
// pack two f32 -> half2 reg; lo half = first arg
__device__ __forceinline__ uint32_t pack_h2(float lo, float hi) {
    uint32_t r;
    asm("cvt.rn.f16x2.f32 %0, %1, %2;" : "=r"(r) : "f"(hi), "f"(lo));
    return r;
}
__device__ __forceinline__ void cp16(uint32_t dst, const void* src) {
    asm volatile("cp.async.cg.shared.global [%0], [%1], 16;" :: "r"(dst), "l"(src));
}
#define CP_COMMIT() asm volatile("cp.async.commit_group;" ::: "memory")
#define CP_WAIT0()  asm volatile("cp.async.wait_group 0;" ::: "memory")
#define CP_WAIT1()  asm volatile("cp.async.wait_group 1;" ::: "memory")

// D += A@B (m16n8k16, fp16 in, fp32 acc)
__device__ __forceinline__ void mma_f16(float* d, const uint32_t* a, const uint32_t* b) {
    asm volatile(
        "mma.sync.aligned.m16n8k16.row.col.f32.f16.f16.f32 "
        "{%0,%1,%2,%3}, {%4,%5,%6,%7}, {%8,%9}, {%0,%1,%2,%3};"
        : "+f"(d[0]), "+f"(d[1]), "+f"(d[2]), "+f"(d[3])
        : "r"(a[0]), "r"(a[1]), "r"(a[2]), "r"(a[3]), "r"(b[0]), "r"(b[1]));
}

// ---------------- prep kernels ----------------
__global__ void f2h_k(const float2* __restrict__ in, uint32_t* __restrict__ out, int n2) {
    int i = blockIdx.x * blockDim.x + threadIdx.x;
    if (i < n2) {
        float2 v = in[i];
        out[i] = pack_h2(v.x, v.y);
    }
}

// out[n][k] = half(in[k][n]); in is [K,N] row-major fp32
__global__ void transpose_h_k(const float* __restrict__ in, __half* __restrict__ out, int K, int N) {
    __shared__ float t[32][33];
    int n0 = blockIdx.x * 32, k0 = blockIdx.y * 32;
    int x = threadIdx.x, y = threadIdx.y;  // 32 x 8
#pragma unroll
    for (int i = 0; i < 32; i += 8)
        t[y + i][x] = in[(size_t)(k0 + y + i) * N + n0 + x];
    __syncthreads();
#pragma unroll
    for (int i = 0; i < 32; i += 8)
        out[(size_t)(n0 + y + i) * K + k0 + x] = __float2half(t[x][y + i]);
}

// Vt[(b*H+h)*64+dh][m] = KV[b*2048+m][1024 + h*64 + dh]
__global__ void vtrans_k(const __half* __restrict__ kv, __half* __restrict__ vt) {
    __shared__ __half t[32][33];
    int m0 = blockIdx.x * 32;
    int z = blockIdx.y;                 // bh*2 + dtile
    int dtile = z & 1, bh = z >> 1;
    int b = bh >> 4, h = bh & 15;
    int d0 = dtile * 32;
    int x = threadIdx.x, y = threadIdx.y;  // 32 x 8
    const __half* src = kv + (size_t)b * SEQ_M * (2 * CDIM) + CDIM + h * DH + d0;
#pragma unroll
    for (int i = 0; i < 32; i += 8)
        t[y + i][x] = src[(size_t)(m0 + y + i) * (2 * CDIM) + x];
    __syncthreads();
    __half* dst = vt + ((size_t)bh * DH + d0) * SEQ_M + m0;
#pragma unroll
    for (int i = 0; i < 32; i += 8)
        dst[(size_t)(y + i) * SEQ_M + x] = t[x][y + i];
}

// ---------------- fp16 mma GEMM: C[M,N] = A[M,K] @ BT[N,K]^T ----------------
// 128x128 tile, BK=32, 256 threads (8 warps: 4 in M x 2 in N; warp = 32x64).
// Smem rows: 32 halves data + 8 pad = pitch 40 halves (80B); cp.async double buffer.
template <int OUT_HALF>
__global__ __launch_bounds__(256) void gemm_h(const __half* __restrict__ A,
                                              const __half* __restrict__ BT,
                                              void* __restrict__ Cv,
                                              int M, int N, int K)
{
    __shared__ __half Asm[2][128 * 40];
    __shared__ __half Bsm[2][128 * 40];
    const int tid = threadIdx.x, lane = tid & 31, wid = tid >> 5;
    const int wm4 = wid & 3, wn = (wid >> 2) * 64;
    const int bx = blockIdx.x * 128, by = blockIdx.y * 128;
    const int r_ = lane >> 2, kq = lane & 3;
    const __half* Ag = A  + (size_t)by * K;
    const __half* Bg = BT + (size_t)bx * K;
    const uint32_t sA = smem_u32(Asm), sB = smem_u32(Bsm);

    float acc[2][8][4];
#pragma unroll
    for (int mi = 0; mi < 2; mi++)
#pragma unroll
        for (int j = 0; j < 8; j++)
#pragma unroll
            for (int q = 0; q < 4; q++) acc[mi][j][q] = 0.0f;

    auto copy_stage = [&](int buf, int k0) {
#pragma unroll
        for (int i = 0; i < 2; i++) {
            int id = tid + i * 256;
            int r = id >> 2, ch = id & 3;
            cp16(sA + buf * 10240 + r * 80 + ch * 16, Ag + (size_t)r * K + k0 + ch * 8);
            cp16(sB + buf * 10240 + r * 80 + ch * 16, Bg + (size_t)r * K + k0 + ch * 8);
        }
    };
    copy_stage(0, 0);
    CP_COMMIT();

    const int ns = K >> 5;
    for (int st = 0; st < ns; st++) {
        const int buf = st & 1;
        __syncthreads();   // all warps done with buffer buf^1 (compute of st-1)
        if (st + 1 < ns) {
            copy_stage(buf ^ 1, (st + 1) * 32);
            CP_COMMIT();
            CP_WAIT1();    // stage st complete (stage st+1 may be in flight)
        } else {
            CP_WAIT0();
        }
        __syncthreads();

        const uint32_t* A32 = (const uint32_t*)Asm[buf];
        const uint32_t* B32 = (const uint32_t*)Bsm[buf];
#pragma unroll
        for (int s = 0; s < 2; s++) {
            uint32_t af[2][4], bf[8][2];
#pragma unroll
            for (int mi = 0; mi < 2; mi++) {
                int row = wm4 * 32 + mi * 16 + r_;
                af[mi][0] = A32[row * 20 + s * 8 + kq];
                af[mi][1] = A32[(row + 8) * 20 + s * 8 + kq];
                af[mi][2] = A32[row * 20 + s * 8 + kq + 4];
                af[mi][3] = A32[(row + 8) * 20 + s * 8 + kq + 4];
            }
#pragma unroll
            for (int j = 0; j < 8; j++) {
                int nb = wn + j * 8 + r_;
                bf[j][0] = B32[nb * 20 + s * 8 + kq];
                bf[j][1] = B32[nb * 20 + s * 8 + kq + 4];
            }
#pragma unroll
            for (int mi = 0; mi < 2; mi++)
#pragma unroll
                for (int j = 0; j < 8; j++)
                    mma_f16(acc[mi][j], af[mi], bf[j]);
        }
    }

    // epilogue
    if (OUT_HALF) {
        __half* C = (__half*)Cv;
#pragma unroll
        for (int mi = 0; mi < 2; mi++) {
            int r0 = by + wm4 * 32 + mi * 16 + r_;
#pragma unroll
            for (int j = 0; j < 8; j++) {
                int col = bx + wn + j * 8 + 2 * kq;
                *(uint32_t*)(C + (size_t)r0 * N + col) =
                    pack_h2(acc[mi][j][0], acc[mi][j][1]);
                *(uint32_t*)(C + (size_t)(r0 + 8) * N + col) =
                    pack_h2(acc[mi][j][2], acc[mi][j][3]);
            }
        }
    } else {
        float* C = (float*)Cv;
#pragma unroll
        for (int mi = 0; mi < 2; mi++) {
            int r0 = by + wm4 * 32 + mi * 16 + r_;
#pragma unroll
            for (int j = 0; j < 8; j++) {
                int col = bx + wn + j * 8 + 2 * kq;
                *(float2*)(C + (size_t)r0 * N + col) =
                    make_float2(acc[mi][j][0], acc[mi][j][1]);
                *(float2*)(C + (size_t)(r0 + 8) * N + col) =
                    make_float2(acc[mi][j][2], acc[mi][j][3]);
            }
        }
    }
}

// ---------------- FlashAttention-2, fp16 mma, register-resident P ----------------
// Grid (B*H=32, N/64=32), 128 threads (4 warps; warp = 16 query rows).
// Smem: Q[64][72h], K[2][64][72h], V(transposed)[2][64][72h] = 45 KB. cp.async pipeline.
__global__ __launch_bounds__(128) void attn_h(const __half* __restrict__ Q,
                                              const __half* __restrict__ KV,
                                              const __half* __restrict__ Vt,
                                              __half* __restrict__ O)
{
    __shared__ __half Qs[64 * 72];
    __shared__ __half Ks[2][64 * 72];
    __shared__ __half Vs[2][64 * 72];
    const int tid = threadIdx.x, lane = tid & 31, wid = tid >> 5;
    const int b = blockIdx.x >> 4, h = blockIdx.x & 15;
    const int n0 = blockIdx.y * 64;
    const int r_ = lane >> 2, kq = lane & 3;
    const uint32_t sQ = smem_u32(Qs), sK = smem_u32(Ks), sV = smem_u32(Vs);

    const __half* Qg = Q  + ((size_t)(b * SEQ_N + n0)) * CDIM + h * DH;
    const __half* Kg = KV + (size_t)b * SEQ_M * (2 * CDIM) + h * DH;
    const __half* Vg = Vt + ((size_t)(b * HEADS + h)) * DH * SEQ_M;

    // Q tile copy (64 rows x 64 dh halves = 128B/row = 8 chunks)
#pragma unroll
    for (int i = 0; i < 4; i++) {
        int id = tid + i * 128, r = id >> 3, ch = id & 7;
        cp16(sQ + r * 144 + ch * 16, Qg + (size_t)r * CDIM + ch * 8);
    }
    auto copyKV = [&](int buf, int mt) {
#pragma unroll
        for (int i = 0; i < 4; i++) {
            int id = tid + i * 128, r = id >> 3, ch = id & 7;
            cp16(sK + buf * 9216 + r * 144 + ch * 16,
                 Kg + (size_t)(mt + r) * (2 * CDIM) + ch * 8);
            cp16(sV + buf * 9216 + r * 144 + ch * 16,
                 Vg + (size_t)r * SEQ_M + mt + ch * 8);
        }
    };
    copyKV(0, 0);
    CP_COMMIT();

    const float SCALE = 0.125f * 1.4426950408889634f;  // Dh^-0.5 * log2(e)
    float m0r = -1e30f, m1r = -1e30f, l0 = 0.0f, l1 = 0.0f;
    float oacc[8][4];
#pragma unroll
    for (int j = 0; j < 8; j++)
#pragma unroll
        for (int q = 0; q < 4; q++) oacc[j][q] = 0.0f;
    uint32_t qf[4][4];

    for (int t = 0; t < SEQ_M / 64; t++) {
        const int buf = t & 1;
        __syncthreads();   // all warps done with buffer buf^1
        if (t + 1 < SEQ_M / 64) {
            copyKV(buf ^ 1, (t + 1) * 64);
            CP_COMMIT();
            CP_WAIT1();    // tile t (and Q on t=0) complete
        } else {
            CP_WAIT0();
        }
        __syncthreads();

        if (t == 0) {
            const uint32_t* Q32 = (const uint32_t*)Qs;
            int row = wid * 16 + r_;
#pragma unroll
            for (int s = 0; s < 4; s++) {
                qf[s][0] = Q32[row * 36 + s * 8 + kq];
                qf[s][1] = Q32[(row + 8) * 36 + s * 8 + kq];
                qf[s][2] = Q32[row * 36 + s * 8 + kq + 4];
                qf[s][3] = Q32[(row + 8) * 36 + s * 8 + kq + 4];
            }
        }
        const uint32_t* K32 = (const uint32_t*)Ks[buf];
        const uint32_t* V32 = (const uint32_t*)Vs[buf];

        // S = Q @ K^T
        float sacc[8][4];
#pragma unroll
        for (int j = 0; j < 8; j++)
#pragma unroll
            for (int q = 0; q < 4; q++) sacc[j][q] = 0.0f;
#pragma unroll
        for (int s = 0; s < 4; s++) {
#pragma unroll
            for (int j = 0; j < 8; j++) {
                uint32_t bf[2];
                int nb = j * 8 + r_;
                bf[0] = K32[nb * 36 + s * 8 + kq];
                bf[1] = K32[nb * 36 + s * 8 + kq + 4];
                mma_f16(sacc[j], qf[s], bf);
            }
        }

        // online softmax (exp2 domain)
        float rm0 = -1e30f, rm1 = -1e30f;
#pragma unroll
        for (int j = 0; j < 8; j++) {
            rm0 = fmaxf(rm0, fmaxf(sacc[j][0], sacc[j][1]));
            rm1 = fmaxf(rm1, fmaxf(sacc[j][2], sacc[j][3]));
        }
        rm0 = fmaxf(rm0, __shfl_xor_sync(0xffffffffu, rm0, 1));
        rm0 = fmaxf(rm0, __shfl_xor_sync(0xffffffffu, rm0, 2));
        rm1 = fmaxf(rm1, __shfl_xor_sync(0xffffffffu, rm1, 1));
        rm1 = fmaxf(rm1, __shfl_xor_sync(0xffffffffu, rm1, 2));
        rm0 *= SCALE; rm1 *= SCALE;
        float mn0 = fmaxf(m0r, rm0), mn1 = fmaxf(m1r, rm1);
        float c0 = exp2_fast(m0r - mn0), c1 = exp2_fast(m1r - mn1);
        m0r = mn0; m1r = mn1;

        float rs0 = 0.0f, rs1 = 0.0f;
        uint32_t pf[4][4];   // register-resident P A-fragments (thread-local mapping!)
#pragma unroll
        for (int j = 0; j < 8; j++) {
            float p00 = exp2_fast(fmaf(sacc[j][0], SCALE, -mn0));
            float p01 = exp2_fast(fmaf(sacc[j][1], SCALE, -mn0));
            float p10 = exp2_fast(fmaf(sacc[j][2], SCALE, -mn1));
            float p11 = exp2_fast(fmaf(sacc[j][3], SCALE, -mn1));
            rs0 += p00 + p01;
            rs1 += p10 + p11;
            int s = j >> 1, hi = (j & 1) * 2;
            pf[s][hi]     = pack_h2(p00, p01);
            pf[s][hi + 1] = pack_h2(p10, p11);
        }
        rs0 += __shfl_xor_sync(0xffffffffu, rs0, 1);
        rs0 += __shfl_xor_sync(0xffffffffu, rs0, 2);
        rs1 += __shfl_xor_sync(0xffffffffu, rs1, 1);
        rs1 += __shfl_xor_sync(0xffffffffu, rs1, 2);
        l0 = l0 * c0 + rs0;
        l1 = l1 * c1 + rs1;
#pragma unroll
        for (int j = 0; j < 8; j++) {
            oacc[j][0] *= c0; oacc[j][1] *= c0;
            oacc[j][2] *= c1; oacc[j][3] *= c1;
        }

        // O += P @ V  (V transposed in smem: rows = dh, k-contiguous along m)
#pragma unroll
        for (int s = 0; s < 4; s++) {
#pragma unroll
            for (int j = 0; j < 8; j++) {
                uint32_t bf[2];
                int nb = j * 8 + r_;
                bf[0] = V32[nb * 36 + s * 8 + kq];
                bf[1] = V32[nb * 36 + s * 8 + kq + 4];
                mma_f16(oacc[j], pf[s], bf);
            }
        }
    }

    // epilogue: normalize, convert to fp16, store
    float inv0 = 1.0f / l0, inv1 = 1.0f / l1;
    int row = n0 + wid * 16 + r_;
    __half* Ob = O + ((size_t)(b * SEQ_N + row)) * CDIM + h * DH;
#pragma unroll
    for (int j = 0; j < 8; j++) {
        int col = j * 8 + 2 * kq;
        *(uint32_t*)(Ob + col) = pack_h2(oacc[j][0] * inv0, oacc[j][1] * inv0);
        *(uint32_t*)(Ob + (size_t)8 * CDIM + col) = pack_h2(oacc[j][2] * inv1, oacc[j][3] * inv1);
    }
}

// ---------------------------------------------------------------------------
extern "C" void kernel_launch(void* const* d_in, const int* in_sizes, int n_in,
                              void* d_out, int out_size)
{
    const float* x   = (const float*)d_in[0];
    const float* ctx = (const float*)d_in[1];
    const float* Wq  = (const float*)d_in[2];
    const float* Wkv = (const float*)d_in[3];
    const float* Wo  = (const float*)d_in[4];
    float* out = (float*)d_out;

    __half *xh, *ch, *Qh, *KVh, *Vt, *AOh, *WqTh, *WkvTh, *WoTh;
    cudaGetSymbolAddress((void**)&xh,    g_xh);
    cudaGetSymbolAddress((void**)&ch,    g_ch);
    cudaGetSymbolAddress((void**)&Qh,    g_Qh);
    cudaGetSymbolAddress((void**)&KVh,   g_KVh);
    cudaGetSymbolAddress((void**)&Vt,    g_Vt);
    cudaGetSymbolAddress((void**)&AOh,   g_AOh);
    cudaGetSymbolAddress((void**)&WqTh,  g_WqTh);
    cudaGetSymbolAddress((void**)&WkvTh, g_WkvTh);
    cudaGetSymbolAddress((void**)&WoTh,  g_WoTh);

    // fp32 -> fp16 conversions
    {
        int n2 = BATCH * SEQ_N * CDIM / 2;
        f2h_k<<<(n2 + 255) / 256, 256>>>((const float2*)x, (uint32_t*)xh, n2);
        n2 = BATCH * SEQ_M * CTXDIM / 2;
        f2h_k<<<(n2 + 255) / 256, 256>>>((const float2*)ctx, (uint32_t*)ch, n2);
    }
    // weight transposes to [N,K] fp16
    transpose_h_k<<<dim3(CDIM / 32, CDIM / 32), dim3(32, 8)>>>(Wq, WqTh, CDIM, CDIM);
    transpose_h_k<<<dim3(2 * CDIM / 32, CTXDIM / 32), dim3(32, 8)>>>(Wkv, WkvTh, CTXDIM, 2 * CDIM);
    transpose_h_k<<<dim3(CDIM / 32, CDIM / 32), dim3(32, 8)>>>(Wo, WoTh, CDIM, CDIM);

    // Q = x @ Wq  (half out)
    gemm_h<1><<<dim3(CDIM / 128, BATCH * SEQ_N / 128), 256>>>(
        xh, WqTh, Qh, BATCH * SEQ_N, CDIM, CDIM);
    // KV = ctx @ Wkv  (half out)
    gemm_h<1><<<dim3(2 * CDIM / 128, BATCH * SEQ_M / 128), 256>>>(
        ch, WkvTh, KVh, BATCH * SEQ_M, 2 * CDIM, CTXDIM);
    // V transpose for attention PV B-fragments
    vtrans_k<<<dim3(SEQ_M / 32, BATCH * HEADS * 2), dim3(32, 8)>>>(KVh, Vt);

    // fused flash attention (fp16 mma, half out)
    attn_h<<<dim3(BATCH * HEADS, SEQ_N / 64), 128>>>(Qh, KVh, Vt, AOh);

    // out = AO @ Wo (fp32 out)
    gemm_h<0><<<dim3(CDIM / 128, BATCH * SEQ_N / 128), 256>>>(
        AOh, WoTh, out, BATCH * SEQ_N, CDIM, CDIM);
}

// round 7
// speedup vs baseline: 3.2222x; 1.0451x over previous
#include <cuda_runtime.h>
#include <cuda_fp16.h>
#include <cstdint>

// x: [2,2048,1024], ctx: [2,2048,768], Wq: [1024,1024], Wkv: [768,2048], Wo: [1024,1024]
#define BATCH 2
#define SEQ_N 2048
#define SEQ_M 2048
#define CDIM 1024
#define CTXDIM 768
#define HEADS 16
#define DH 64

// ---------------- device scratch (allocation-free rule) ----------------
__device__ __half g_xh [BATCH * SEQ_N * CDIM];
__device__ __half g_ch [BATCH * SEQ_M * CTXDIM];
__device__ __half g_Qh [BATCH * SEQ_N * CDIM];
__device__ __half g_KVh[BATCH * SEQ_M * 2 * CDIM];
__device__ __half g_Vt [BATCH * HEADS * DH * SEQ_M];
__device__ __half g_AOh[BATCH * SEQ_N * CDIM];
__device__ __half g_WqTh [CDIM * CDIM];
__device__ __half g_WkvTh[2 * CDIM * CTXDIM];
__device__ __half g_WoTh [CDIM * CDIM];

// ---------------- helpers ----------------
__device__ __forceinline__ uint32_t smem_u32(const void* p) {
    uint32_t a;
    asm("{ .reg .u64 t; cvta.to.shared.u64 t, %1; cvt.u32.u64 %0, t; }" : "=r"(a) : "l"(p));
    return a;
}
__device__ __forceinline__ float exp2_fast(float x) {
    float r;
    asm("ex2.approx.ftz.f32 %0, %1;" : "=f"(r) : "f"(x));
    return r;
}
__device__ __forceinline__ uint32_t pack_h2(float lo, float hi) {
    uint32_t r;
    asm("cvt.rn.f16x2.f32 %0, %1, %2;" : "=r"(r) : "f"(hi), "f"(lo));
    return r;
}
__device__ __forceinline__ void cp16(uint32_t dst, const void* src) {
    asm volatile("cp.async.cg.shared.global [%0], [%1], 16;" :: "r"(dst), "l"(src));
}
#define CP_COMMIT() asm volatile("cp.async.commit_group;" ::: "memory")
#define CP_WAIT0()  asm volatile("cp.async.wait_group 0;" ::: "memory")
#define CP_WAIT1()  asm volatile("cp.async.wait_group 1;" ::: "memory")

__device__ __forceinline__ void ldmx4(uint32_t* r, uint32_t a) {
    asm volatile("ldmatrix.sync.aligned.m8n8.x4.shared.b16 {%0,%1,%2,%3}, [%4];"
        : "=r"(r[0]), "=r"(r[1]), "=r"(r[2]), "=r"(r[3]) : "r"(a));
}

// D += A@B (m16n8k16, fp16 in, fp32 acc)
__device__ __forceinline__ void mma_f16(float* d, const uint32_t* a, const uint32_t* b) {
    asm volatile(
        "mma.sync.aligned.m16n8k16.row.col.f32.f16.f16.f32 "
        "{%0,%1,%2,%3}, {%4,%5,%6,%7}, {%8,%9}, {%0,%1,%2,%3};"
        : "+f"(d[0]), "+f"(d[1]), "+f"(d[2]), "+f"(d[3])
        : "r"(a[0]), "r"(a[1]), "r"(a[2]), "r"(a[3]), "r"(b[0]), "r"(b[1]));
}

// ---------------- prep kernels ----------------
__global__ void f2h_k(const float2* __restrict__ in, uint32_t* __restrict__ out, int n2) {
    int i = blockIdx.x * blockDim.x + threadIdx.x;
    if (i < n2) {
        float2 v = in[i];
        out[i] = pack_h2(v.x, v.y);
    }
}

__global__ void transpose_h_k(const float* __restrict__ in, __half* __restrict__ out, int K, int N) {
    __shared__ float t[32][33];
    int n0 = blockIdx.x * 32, k0 = blockIdx.y * 32;
    int x = threadIdx.x, y = threadIdx.y;
#pragma unroll
    for (int i = 0; i < 32; i += 8)
        t[y + i][x] = in[(size_t)(k0 + y + i) * N + n0 + x];
    __syncthreads();
#pragma unroll
    for (int i = 0; i < 32; i += 8)
        out[(size_t)(n0 + y + i) * K + k0 + x] = __float2half(t[x][y + i]);
}

// Vt[(b*H+h)*64+dh][m] = KV[b*2048+m][1024 + h*64 + dh]
__global__ void vtrans_k(const __half* __restrict__ kv, __half* __restrict__ vt) {
    __shared__ __half t[32][33];
    int m0 = blockIdx.x * 32;
    int z = blockIdx.y;
    int dtile = z & 1, bh = z >> 1;
    int b = bh >> 4, h = bh & 15;
    int d0 = dtile * 32;
    int x = threadIdx.x, y = threadIdx.y;
    const __half* src = kv + (size_t)b * SEQ_M * (2 * CDIM) + CDIM + h * DH + d0;
#pragma unroll
    for (int i = 0; i < 32; i += 8)
        t[y + i][x] = src[(size_t)(m0 + y + i) * (2 * CDIM) + x];
    __syncthreads();
    __half* dst = vt + ((size_t)bh * DH + d0) * SEQ_M + m0;
#pragma unroll
    for (int i = 0; i < 32; i += 8)
        dst[(size_t)(y + i) * SEQ_M + x] = t[x][y + i];
}

// ---------------- fp16 mma GEMM: C[M,N] = A[M,K] @ BT[N,K]^T ----------------
// 128x128 tile, BK=32, 256 threads (8 warps: 4 in M x 2 in N; warp = 32x64).
// Pitch 40 halves (80B) -> ldmatrix conflict-free. cp.async double buffer.
template <int OUT_HALF>
__global__ __launch_bounds__(256) void gemm_h(const __half* __restrict__ A,
                                              const __half* __restrict__ BT,
                                              void* __restrict__ Cv,
                                              int M, int N, int K)
{
    __shared__ __half Asm[2][128 * 40];
    __shared__ __half Bsm[2][128 * 40];
    const int tid = threadIdx.x, lane = tid & 31, wid = tid >> 5;
    const int wm4 = wid & 3, wn = (wid >> 2) * 64;
    const int bx = blockIdx.x * 128, by = blockIdx.y * 128;
    const int r_ = lane >> 2, kq = lane & 3;
    const __half* Ag = A  + (size_t)by * K;
    const __half* Bg = BT + (size_t)bx * K;
    const uint32_t sA = smem_u32(Asm), sB = smem_u32(Bsm);

    // ldmatrix per-lane address components
    const int laneRowA = (lane & 7) + ((lane >> 3) & 1) * 8;  // row within 16
    const int kA = (lane >> 4) * 8;                            // k chunk within 16
    const int laneRowB = (lane & 7) + (lane >> 4) * 8;         // row within 16 (2 n-tiles)
    const int kB = ((lane >> 3) & 1) * 8;

    float acc[2][8][4];
#pragma unroll
    for (int mi = 0; mi < 2; mi++)
#pragma unroll
        for (int j = 0; j < 8; j++)
#pragma unroll
            for (int q = 0; q < 4; q++) acc[mi][j][q] = 0.0f;

    auto copy_stage = [&](int buf, int k0) {
#pragma unroll
        for (int i = 0; i < 2; i++) {
            int id = tid + i * 256;
            int r = id >> 2, ch = id & 3;
            cp16(sA + buf * 10240 + r * 80 + ch * 16, Ag + (size_t)r * K + k0 + ch * 8);
            cp16(sB + buf * 10240 + r * 80 + ch * 16, Bg + (size_t)r * K + k0 + ch * 8);
        }
    };
    copy_stage(0, 0);
    CP_COMMIT();

    const int ns = K >> 5;
    for (int st = 0; st < ns; st++) {
        const int buf = st & 1;
        __syncthreads();
        if (st + 1 < ns) {
            copy_stage(buf ^ 1, (st + 1) * 32);
            CP_COMMIT();
            CP_WAIT1();
        } else {
            CP_WAIT0();
        }
        __syncthreads();

        const uint32_t bufA = sA + buf * 10240;
        const uint32_t bufB = sB + buf * 10240;
#pragma unroll
        for (int s = 0; s < 2; s++) {
            uint32_t af[2][4], bq[4][4];
#pragma unroll
            for (int mi = 0; mi < 2; mi++) {
                int row = wm4 * 32 + mi * 16 + laneRowA;
                ldmx4(af[mi], bufA + (row * 40 + s * 16 + kA) * 2);
            }
#pragma unroll
            for (int jp = 0; jp < 4; jp++) {
                int row = wn + jp * 16 + laneRowB;
                ldmx4(bq[jp], bufB + (row * 40 + s * 16 + kB) * 2);
            }
#pragma unroll
            for (int mi = 0; mi < 2; mi++)
#pragma unroll
                for (int j = 0; j < 8; j++)
                    mma_f16(acc[mi][j], af[mi], &bq[j >> 1][(j & 1) * 2]);
        }
    }

    if (OUT_HALF) {
        __half* C = (__half*)Cv;
#pragma unroll
        for (int mi = 0; mi < 2; mi++) {
            int r0 = by + wm4 * 32 + mi * 16 + r_;
#pragma unroll
            for (int j = 0; j < 8; j++) {
                int col = bx + wn + j * 8 + 2 * kq;
                *(uint32_t*)(C + (size_t)r0 * N + col) =
                    pack_h2(acc[mi][j][0], acc[mi][j][1]);
                *(uint32_t*)(C + (size_t)(r0 + 8) * N + col) =
                    pack_h2(acc[mi][j][2], acc[mi][j][3]);
            }
        }
    } else {
        float* C = (float*)Cv;
#pragma unroll
        for (int mi = 0; mi < 2; mi++) {
            int r0 = by + wm4 * 32 + mi * 16 + r_;
#pragma unroll
            for (int j = 0; j < 8; j++) {
                int col = bx + wn + j * 8 + 2 * kq;
                *(float2*)(C + (size_t)r0 * N + col) =
                    make_float2(acc[mi][j][0], acc[mi][j][1]);
                *(float2*)(C + (size_t)(r0 + 8) * N + col) =
                    make_float2(acc[mi][j][2], acc[mi][j][3]);
            }
        }
    }
}

// ---------------- FlashAttention-2, fp16 mma, ldmatrix fragments ----------------
// Grid (B*H=32, N/64=32), 128 threads (4 warps; warp = 16 query rows).
// Pitch 72 halves (144B) -> ldmatrix conflict-free. cp.async double buffer.
__global__ __launch_bounds__(128) void attn_h(const __half* __restrict__ Q,
                                              const __half* __restrict__ KV,
                                              const __half* __restrict__ Vt,
                                              __half* __restrict__ O)
{
    __shared__ __half Qs[64 * 72];
    __shared__ __half Ks[2][64 * 72];
    __shared__ __half Vs[2][64 * 72];
    const int tid = threadIdx.x, lane = tid & 31, wid = tid >> 5;
    const int b = blockIdx.x >> 4, h = blockIdx.x & 15;
    const int n0 = blockIdx.y * 64;
    const int r_ = lane >> 2, kq = lane & 3;
    const uint32_t sQ = smem_u32(Qs), sK = smem_u32(Ks), sV = smem_u32(Vs);

    const int laneRowA = (lane & 7) + ((lane >> 3) & 1) * 8;
    const int kA = (lane >> 4) * 8;
    const int laneRowB = (lane & 7) + (lane >> 4) * 8;
    const int kB = ((lane >> 3) & 1) * 8;

    const __half* Qg = Q  + ((size_t)(b * SEQ_N + n0)) * CDIM + h * DH;
    const __half* Kg = KV + (size_t)b * SEQ_M * (2 * CDIM) + h * DH;
    const __half* Vg = Vt + ((size_t)(b * HEADS + h)) * DH * SEQ_M;

#pragma unroll
    for (int i = 0; i < 4; i++) {
        int id = tid + i * 128, r = id >> 3, ch = id & 7;
        cp16(sQ + r * 144 + ch * 16, Qg + (size_t)r * CDIM + ch * 8);
    }
    auto copyKV = [&](int buf, int mt) {
#pragma unroll
        for (int i = 0; i < 4; i++) {
            int id = tid + i * 128, r = id >> 3, ch = id & 7;
            cp16(sK + buf * 9216 + r * 144 + ch * 16,
                 Kg + (size_t)(mt + r) * (2 * CDIM) + ch * 8);
            cp16(sV + buf * 9216 + r * 144 + ch * 16,
                 Vg + (size_t)r * SEQ_M + mt + ch * 8);
        }
    };
    copyKV(0, 0);
    CP_COMMIT();

    const float SCALE = 0.125f * 1.4426950408889634f;
    float m0r = -1e30f, m1r = -1e30f, l0 = 0.0f, l1 = 0.0f;
    float oacc[8][4];
#pragma unroll
    for (int j = 0; j < 8; j++)
#pragma unroll
        for (int q = 0; q < 4; q++) oacc[j][q] = 0.0f;
    uint32_t qf[4][4];

    for (int t = 0; t < SEQ_M / 64; t++) {
        const int buf = t & 1;
        __syncthreads();
        if (t + 1 < SEQ_M / 64) {
            copyKV(buf ^ 1, (t + 1) * 64);
            CP_COMMIT();
            CP_WAIT1();
        } else {
            CP_WAIT0();
        }
        __syncthreads();

        if (t == 0) {
            int row = wid * 16 + laneRowA;
#pragma unroll
            for (int s = 0; s < 4; s++)
                ldmx4(qf[s], sQ + (row * 72 + s * 16 + kA) * 2);
        }
        const uint32_t bufK = sK + buf * 9216;
        const uint32_t bufV = sV + buf * 9216;

        // S = Q @ K^T
        float sacc[8][4];
#pragma unroll
        for (int j = 0; j < 8; j++)
#pragma unroll
            for (int q = 0; q < 4; q++) sacc[j][q] = 0.0f;
#pragma unroll
        for (int s = 0; s < 4; s++) {
            uint32_t bq[4][4];
#pragma unroll
            for (int jp = 0; jp < 4; jp++) {
                int row = jp * 16 + laneRowB;
                ldmx4(bq[jp], bufK + (row * 72 + s * 16 + kB) * 2);
            }
#pragma unroll
            for (int j = 0; j < 8; j++)
                mma_f16(sacc[j], qf[s], &bq[j >> 1][(j & 1) * 2]);
        }

        // online softmax (exp2 domain)
        float rm0 = -1e30f, rm1 = -1e30f;
#pragma unroll
        for (int j = 0; j < 8; j++) {
            rm0 = fmaxf(rm0, fmaxf(sacc[j][0], sacc[j][1]));
            rm1 = fmaxf(rm1, fmaxf(sacc[j][2], sacc[j][3]));
        }
        rm0 = fmaxf(rm0, __shfl_xor_sync(0xffffffffu, rm0, 1));
        rm0 = fmaxf(rm0, __shfl_xor_sync(0xffffffffu, rm0, 2));
        rm1 = fmaxf(rm1, __shfl_xor_sync(0xffffffffu, rm1, 1));
        rm1 = fmaxf(rm1, __shfl_xor_sync(0xffffffffu, rm1, 2));
        rm0 *= SCALE; rm1 *= SCALE;
        float mn0 = fmaxf(m0r, rm0), mn1 = fmaxf(m1r, rm1);
        float c0 = exp2_fast(m0r - mn0), c1 = exp2_fast(m1r - mn1);
        m0r = mn0; m1r = mn1;

        float rs0 = 0.0f, rs1 = 0.0f;
        uint32_t pf[4][4];   // register-resident P A-fragments
#pragma unroll
        for (int j = 0; j < 8; j++) {
            float p00 = exp2_fast(fmaf(sacc[j][0], SCALE, -mn0));
            float p01 = exp2_fast(fmaf(sacc[j][1], SCALE, -mn0));
            float p10 = exp2_fast(fmaf(sacc[j][2], SCALE, -mn1));
            float p11 = exp2_fast(fmaf(sacc[j][3], SCALE, -mn1));
            rs0 += p00 + p01;
            rs1 += p10 + p11;
            int s = j >> 1, hi = (j & 1) * 2;
            pf[s][hi]     = pack_h2(p00, p01);
            pf[s][hi + 1] = pack_h2(p10, p11);
        }
        rs0 += __shfl_xor_sync(0xffffffffu, rs0, 1);
        rs0 += __shfl_xor_sync(0xffffffffu, rs0, 2);
        rs1 += __shfl_xor_sync(0xffffffffu, rs1, 1);
        rs1 += __shfl_xor_sync(0xffffffffu, rs1, 2);
        l0 = l0 * c0 + rs0;
        l1 = l1 * c1 + rs1;
#pragma unroll
        for (int j = 0; j < 8; j++) {
            oacc[j][0] *= c0; oacc[j][1] *= c0;
            oacc[j][2] *= c1; oacc[j][3] *= c1;
        }

        // O += P @ V  (V transposed: smem rows = dh, contiguous along m)
#pragma unroll
        for (int s = 0; s < 4; s++) {
            uint32_t bq[4][4];
#pragma unroll
            for (int jp = 0; jp < 4; jp++) {
                int row = jp * 16 + laneRowB;
                ldmx4(bq[jp], bufV + (row * 72 + s * 16 + kB) * 2);
            }
#pragma unroll
            for (int j = 0; j < 8; j++)
                mma_f16(oacc[j], pf[s], &bq[j >> 1][(j & 1) * 2]);
        }
    }

    float inv0 = 1.0f / l0, inv1 = 1.0f / l1;
    int row = n0 + wid * 16 + r_;
    __half* Ob = O + ((size_t)(b * SEQ_N + row)) * CDIM + h * DH;
#pragma unroll
    for (int j = 0; j < 8; j++) {
        int col = j * 8 + 2 * kq;
        *(uint32_t*)(Ob + col) = pack_h2(oacc[j][0] * inv0, oacc[j][1] * inv0);
        *(uint32_t*)(Ob + (size_t)8 * CDIM + col) = pack_h2(oacc[j][2] * inv1, oacc[j][3] * inv1);
    }
}

// ---------------------------------------------------------------------------
extern "C" void kernel_launch(void* const* d_in, const int* in_sizes, int n_in,
                              void* d_out, int out_size)
{
    const float* x   = (const float*)d_in[0];
    const float* ctx = (const float*)d_in[1];
    const float* Wq  = (const float*)d_in[2];
    const float* Wkv = (const float*)d_in[3];
    const float* Wo  = (const float*)d_in[4];
    float* out = (float*)d_out;

    __half *xh, *ch, *Qh, *KVh, *Vt, *AOh, *WqTh, *WkvTh, *WoTh;
    cudaGetSymbolAddress((void**)&xh,    g_xh);
    cudaGetSymbolAddress((void**)&ch,    g_ch);
    cudaGetSymbolAddress((void**)&Qh,    g_Qh);
    cudaGetSymbolAddress((void**)&KVh,   g_KVh);
    cudaGetSymbolAddress((void**)&Vt,    g_Vt);
    cudaGetSymbolAddress((void**)&AOh,   g_AOh);
    cudaGetSymbolAddress((void**)&WqTh,  g_WqTh);
    cudaGetSymbolAddress((void**)&WkvTh, g_WkvTh);
    cudaGetSymbolAddress((void**)&WoTh,  g_WoTh);

    {
        int n2 = BATCH * SEQ_N * CDIM / 2;
        f2h_k<<<(n2 + 255) / 256, 256>>>((const float2*)x, (uint32_t*)xh, n2);
        n2 = BATCH * SEQ_M * CTXDIM / 2;
        f2h_k<<<(n2 + 255) / 256, 256>>>((const float2*)ctx, (uint32_t*)ch, n2);
    }
    transpose_h_k<<<dim3(CDIM / 32, CDIM / 32), dim3(32, 8)>>>(Wq, WqTh, CDIM, CDIM);
    transpose_h_k<<<dim3(2 * CDIM / 32, CTXDIM / 32), dim3(32, 8)>>>(Wkv, WkvTh, CTXDIM, 2 * CDIM);
    transpose_h_k<<<dim3(CDIM / 32, CDIM / 32), dim3(32, 8)>>>(Wo, WoTh, CDIM, CDIM);

    gemm_h<1><<<dim3(CDIM / 128, BATCH * SEQ_N / 128), 256>>>(
        xh, WqTh, Qh, BATCH * SEQ_N, CDIM, CDIM);
    gemm_h<1><<<dim3(2 * CDIM / 128, BATCH * SEQ_M / 128), 256>>>(
        ch, WkvTh, KVh, BATCH * SEQ_M, 2 * CDIM, CTXDIM);
    vtrans_k<<<dim3(SEQ_M / 32, BATCH * HEADS * 2), dim3(32, 8)>>>(KVh, Vt);

    attn_h<<<dim3(BATCH * HEADS, SEQ_N / 64), 128>>>(Qh, KVh, Vt, AOh);

    gemm_h<0><<<dim3(CDIM / 128, BATCH * SEQ_N / 128), 256>>>(
        AOh, WoTh, out, BATCH * SEQ_N, CDIM, CDIM);
}

// round 8
// speedup vs baseline: 3.3602x; 1.0428x over previous
#include <cuda_runtime.h>
#include <cuda_fp16.h>
#include <cstdint>

// x: [2,2048,1024], ctx: [2,2048,768], Wq: [1024,1024], Wkv: [768,2048], Wo: [1024,1024]
#define BATCH 2
#define SEQ_N 2048
#define SEQ_M 2048
#define CDIM 1024
#define CTXDIM 768
#define HEADS 16
#define DH 64

// ---------------- device scratch (allocation-free rule) ----------------
__device__ __half g_xh [BATCH * SEQ_N * CDIM];
__device__ __half g_ch [BATCH * SEQ_M * CTXDIM];
__device__ __half g_Qh [BATCH * SEQ_N * CDIM];
__device__ __half g_KVh[BATCH * SEQ_M * 2 * CDIM];
__device__ __half g_AOh[BATCH * SEQ_N * CDIM];
__device__ __half g_WqTh [CDIM * CDIM];
__device__ __half g_WkvTh[2 * CDIM * CTXDIM];
__device__ __half g_WoTh [CDIM * CDIM];

// ---------------- helpers ----------------
__device__ __forceinline__ uint32_t smem_u32(const void* p) {
    uint32_t a;
    asm("{ .reg .u64 t; cvta.to.shared.u64 t, %1; cvt.u32.u64 %0, t; }" : "=r"(a) : "l"(p));
    return a;
}
__device__ __forceinline__ float exp2_fast(float x) {
    float r;
    asm("ex2.approx.ftz.f32 %0, %1;" : "=f"(r) : "f"(x));
    return r;
}
__device__ __forceinline__ uint32_t pack_h2(float lo, float hi) {
    uint32_t r;
    asm("cvt.rn.f16x2.f32 %0, %1, %2;" : "=r"(r) : "f"(hi), "f"(lo));
    return r;
}
__device__ __forceinline__ void cp16(uint32_t dst, const void* src) {
    asm volatile("cp.async.cg.shared.global [%0], [%1], 16;" :: "r"(dst), "l"(src));
}
#define CP_COMMIT() asm volatile("cp.async.commit_group;" ::: "memory")
#define CP_WAIT0()  asm volatile("cp.async.wait_group 0;" ::: "memory")
#define CP_WAIT1()  asm volatile("cp.async.wait_group 1;" ::: "memory")

__device__ __forceinline__ void ldmx4(uint32_t* r, uint32_t a) {
    asm volatile("ldmatrix.sync.aligned.m8n8.x4.shared.b16 {%0,%1,%2,%3}, [%4];"
        : "=r"(r[0]), "=r"(r[1]), "=r"(r[2]), "=r"(r[3]) : "r"(a));
}
__device__ __forceinline__ void ldmx4t(uint32_t* r, uint32_t a) {
    asm volatile("ldmatrix.sync.aligned.m8n8.x4.trans.shared.b16 {%0,%1,%2,%3}, [%4];"
        : "=r"(r[0]), "=r"(r[1]), "=r"(r[2]), "=r"(r[3]) : "r"(a));
}

// D += A@B (m16n8k16, fp16 in, fp32 acc)
__device__ __forceinline__ void mma_f16(float* d, const uint32_t* a, const uint32_t* b) {
    asm volatile(
        "mma.sync.aligned.m16n8k16.row.col.f32.f16.f16.f32 "
        "{%0,%1,%2,%3}, {%4,%5,%6,%7}, {%8,%9}, {%0,%1,%2,%3};"
        : "+f"(d[0]), "+f"(d[1]), "+f"(d[2]), "+f"(d[3])
        : "r"(a[0]), "r"(a[1]), "r"(a[2]), "r"(a[3]), "r"(b[0]), "r"(b[1]));
}

// ---------------- fused prep kernels ----------------
// one kernel converts both x and ctx fp32->fp16
__global__ void f2h_all(const float2* __restrict__ x, uint32_t* __restrict__ xh, int n1,
                        const float2* __restrict__ c, uint32_t* __restrict__ ch, int n2) {
    int i = blockIdx.x * blockDim.x + threadIdx.x;
    if (i < n1) {
        float2 v = x[i];
        xh[i] = pack_h2(v.x, v.y);
    } else if (i < n1 + n2) {
        int j = i - n1;
        float2 v = c[j];
        ch[j] = pack_h2(v.x, v.y);
    }
}

// one kernel transposes all three weights (z selects matrix); out[n][k] = half(in[k][n])
__global__ void wtrans_all(const float* __restrict__ Wq,  __half* __restrict__ WqT,
                           const float* __restrict__ Wkv, __half* __restrict__ WkvT,
                           const float* __restrict__ Wo,  __half* __restrict__ WoT) {
    const float* in;
    __half* out;
    int K, N;
    if (blockIdx.z == 0)      { in = Wq;  out = WqT;  K = CDIM;   N = CDIM; }
    else if (blockIdx.z == 1) { in = Wkv; out = WkvT; K = CTXDIM; N = 2 * CDIM; }
    else                      { in = Wo;  out = WoT;  K = CDIM;   N = CDIM; }
    int n0 = blockIdx.x * 32, k0 = blockIdx.y * 32;
    if (n0 >= N || k0 >= K) return;
    __shared__ float t[32][33];
    int x = threadIdx.x, y = threadIdx.y;
#pragma unroll
    for (int i = 0; i < 32; i += 8)
        t[y + i][x] = in[(size_t)(k0 + y + i) * N + n0 + x];
    __syncthreads();
#pragma unroll
    for (int i = 0; i < 32; i += 8)
        out[(size_t)(n0 + y + i) * K + k0 + x] = __float2half(t[x][y + i]);
}

// ---------------- fp16 mma GEMM: C[M,N] = A[M,K] @ BT[N,K]^T ----------------
// 128x128 tile, BK=32, 256 threads (8 warps: 4 in M x 2 in N; warp = 32x64).
// Pitch 40 halves (80B) -> ldmatrix conflict-free. cp.async double buffer.
template <int OUT_HALF>
__global__ __launch_bounds__(256) void gemm_h(const __half* __restrict__ A,
                                              const __half* __restrict__ BT,
                                              void* __restrict__ Cv,
                                              int M, int N, int K)
{
    __shared__ __half Asm[2][128 * 40];
    __shared__ __half Bsm[2][128 * 40];
    const int tid = threadIdx.x, lane = tid & 31, wid = tid >> 5;
    const int wm4 = wid & 3, wn = (wid >> 2) * 64;
    const int bx = blockIdx.x * 128, by = blockIdx.y * 128;
    const int r_ = lane >> 2, kq = lane & 3;
    const __half* Ag = A  + (size_t)by * K;
    const __half* Bg = BT + (size_t)bx * K;
    const uint32_t sA = smem_u32(Asm), sB = smem_u32(Bsm);

    const int laneRowA = (lane & 7) + ((lane >> 3) & 1) * 8;
    const int kA = (lane >> 4) * 8;
    const int laneRowB = (lane & 7) + (lane >> 4) * 8;
    const int kB = ((lane >> 3) & 1) * 8;

    float acc[2][8][4];
#pragma unroll
    for (int mi = 0; mi < 2; mi++)
#pragma unroll
        for (int j = 0; j < 8; j++)
#pragma unroll
            for (int q = 0; q < 4; q++) acc[mi][j][q] = 0.0f;

    auto copy_stage = [&](int buf, int k0) {
#pragma unroll
        for (int i = 0; i < 2; i++) {
            int id = tid + i * 256;
            int r = id >> 2, ch = id & 3;
            cp16(sA + buf * 10240 + r * 80 + ch * 16, Ag + (size_t)r * K + k0 + ch * 8);
            cp16(sB + buf * 10240 + r * 80 + ch * 16, Bg + (size_t)r * K + k0 + ch * 8);
        }
    };
    copy_stage(0, 0);
    CP_COMMIT();

    const int ns = K >> 5;
    for (int st = 0; st < ns; st++) {
        const int buf = st & 1;
        __syncthreads();
        if (st + 1 < ns) {
            copy_stage(buf ^ 1, (st + 1) * 32);
            CP_COMMIT();
            CP_WAIT1();
        } else {
            CP_WAIT0();
        }
        __syncthreads();

        const uint32_t bufA = sA + buf * 10240;
        const uint32_t bufB = sB + buf * 10240;
#pragma unroll
        for (int s = 0; s < 2; s++) {
            uint32_t af[2][4], bq[4][4];
#pragma unroll
            for (int mi = 0; mi < 2; mi++) {
                int row = wm4 * 32 + mi * 16 + laneRowA;
                ldmx4(af[mi], bufA + (row * 40 + s * 16 + kA) * 2);
            }
#pragma unroll
            for (int jp = 0; jp < 4; jp++) {
                int row = wn + jp * 16 + laneRowB;
                ldmx4(bq[jp], bufB + (row * 40 + s * 16 + kB) * 2);
            }
#pragma unroll
            for (int mi = 0; mi < 2; mi++)
#pragma unroll
                for (int j = 0; j < 8; j++)
                    mma_f16(acc[mi][j], af[mi], &bq[j >> 1][(j & 1) * 2]);
        }
    }

    if (OUT_HALF) {
        __half* C = (__half*)Cv;
#pragma unroll
        for (int mi = 0; mi < 2; mi++) {
            int r0 = by + wm4 * 32 + mi * 16 + r_;
#pragma unroll
            for (int j = 0; j < 8; j++) {
                int col = bx + wn + j * 8 + 2 * kq;
                *(uint32_t*)(C + (size_t)r0 * N + col) =
                    pack_h2(acc[mi][j][0], acc[mi][j][1]);
                *(uint32_t*)(C + (size_t)(r0 + 8) * N + col) =
                    pack_h2(acc[mi][j][2], acc[mi][j][3]);
            }
        }
    } else {
        float* C = (float*)Cv;
#pragma unroll
        for (int mi = 0; mi < 2; mi++) {
            int r0 = by + wm4 * 32 + mi * 16 + r_;
#pragma unroll
            for (int j = 0; j < 8; j++) {
                int col = bx + wn + j * 8 + 2 * kq;
                *(float2*)(C + (size_t)r0 * N + col) =
                    make_float2(acc[mi][j][0], acc[mi][j][1]);
                *(float2*)(C + (size_t)(r0 + 8) * N + col) =
                    make_float2(acc[mi][j][2], acc[mi][j][3]);
            }
        }
    }
}

// ---------------- FlashAttention-2, fp16 mma, V via ldmatrix.trans ----------------
// Grid (B*H=32, N/64=32), 128 threads (4 warps; warp = 16 query rows).
// V is consumed row-major [m][dh] directly from KV; PV B-fragments via ldmatrix.trans.
__global__ __launch_bounds__(128) void attn_h(const __half* __restrict__ Q,
                                              const __half* __restrict__ KV,
                                              __half* __restrict__ O)
{
    __shared__ __half Qs[64 * 72];
    __shared__ __half Ks[2][64 * 72];
    __shared__ __half Vs[2][64 * 72];
    const int tid = threadIdx.x, lane = tid & 31, wid = tid >> 5;
    const int b = blockIdx.x >> 4, h = blockIdx.x & 15;
    const int n0 = blockIdx.y * 64;
    const int r_ = lane >> 2, kq = lane & 3;
    const uint32_t sQ = smem_u32(Qs), sK = smem_u32(Ks), sV = smem_u32(Vs);

    const int laneRowA = (lane & 7) + ((lane >> 3) & 1) * 8;
    const int kA = (lane >> 4) * 8;
    const int laneRowB = (lane & 7) + (lane >> 4) * 8;
    const int kB = ((lane >> 3) & 1) * 8;
    const int laneRowV = lane & 15;            // k (m-position) row for trans load
    const int colV = (lane >> 4) * 8;          // dh column offset

    const __half* Qg = Q  + ((size_t)(b * SEQ_N + n0)) * CDIM + h * DH;
    const __half* Kg = KV + (size_t)b * SEQ_M * (2 * CDIM) + h * DH;
    const __half* Vg = Kg + CDIM;              // V columns of same KV rows

#pragma unroll
    for (int i = 0; i < 4; i++) {
        int id = tid + i * 128, r = id >> 3, ch = id & 7;
        cp16(sQ + r * 144 + ch * 16, Qg + (size_t)r * CDIM + ch * 8);
    }
    auto copyKV = [&](int buf, int mt) {
#pragma unroll
        for (int i = 0; i < 4; i++) {
            int id = tid + i * 128, r = id >> 3, ch = id & 7;
            cp16(sK + buf * 9216 + r * 144 + ch * 16,
                 Kg + (size_t)(mt + r) * (2 * CDIM) + ch * 8);
            cp16(sV + buf * 9216 + r * 144 + ch * 16,
                 Vg + (size_t)(mt + r) * (2 * CDIM) + ch * 8);
        }
    };
    copyKV(0, 0);
    CP_COMMIT();

    const float SCALE = 0.125f * 1.4426950408889634f;
    float m0r = -1e30f, m1r = -1e30f, l0 = 0.0f, l1 = 0.0f;
    float oacc[8][4];
#pragma unroll
    for (int j = 0; j < 8; j++)
#pragma unroll
        for (int q = 0; q < 4; q++) oacc[j][q] = 0.0f;
    uint32_t qf[4][4];

    for (int t = 0; t < SEQ_M / 64; t++) {
        const int buf = t & 1;
        __syncthreads();
        if (t + 1 < SEQ_M / 64) {
            copyKV(buf ^ 1, (t + 1) * 64);
            CP_COMMIT();
            CP_WAIT1();
        } else {
            CP_WAIT0();
        }
        __syncthreads();

        if (t == 0) {
            int row = wid * 16 + laneRowA;
#pragma unroll
            for (int s = 0; s < 4; s++)
                ldmx4(qf[s], sQ + (row * 72 + s * 16 + kA) * 2);
        }
        const uint32_t bufK = sK + buf * 9216;
        const uint32_t bufV = sV + buf * 9216;

        // S = Q @ K^T
        float sacc[8][4];
#pragma unroll
        for (int j = 0; j < 8; j++)
#pragma unroll
            for (int q = 0; q < 4; q++) sacc[j][q] = 0.0f;
#pragma unroll
        for (int s = 0; s < 4; s++) {
            uint32_t bq[4][4];
#pragma unroll
            for (int jp = 0; jp < 4; jp++) {
                int row = jp * 16 + laneRowB;
                ldmx4(bq[jp], bufK + (row * 72 + s * 16 + kB) * 2);
            }
#pragma unroll
            for (int j = 0; j < 8; j++)
                mma_f16(sacc[j], qf[s], &bq[j >> 1][(j & 1) * 2]);
        }

        // online softmax (exp2 domain)
        float rm0 = -1e30f, rm1 = -1e30f;
#pragma unroll
        for (int j = 0; j < 8; j++) {
            rm0 = fmaxf(rm0, fmaxf(sacc[j][0], sacc[j][1]));
            rm1 = fmaxf(rm1, fmaxf(sacc[j][2], sacc[j][3]));
        }
        rm0 = fmaxf(rm0, __shfl_xor_sync(0xffffffffu, rm0, 1));
        rm0 = fmaxf(rm0, __shfl_xor_sync(0xffffffffu, rm0, 2));
        rm1 = fmaxf(rm1, __shfl_xor_sync(0xffffffffu, rm1, 1));
        rm1 = fmaxf(rm1, __shfl_xor_sync(0xffffffffu, rm1, 2));
        rm0 *= SCALE; rm1 *= SCALE;
        float mn0 = fmaxf(m0r, rm0), mn1 = fmaxf(m1r, rm1);
        float c0 = exp2_fast(m0r - mn0), c1 = exp2_fast(m1r - mn1);
        m0r = mn0; m1r = mn1;

        float rs0 = 0.0f, rs1 = 0.0f;
        uint32_t pf[4][4];   // register-resident P A-fragments
#pragma unroll
        for (int j = 0; j < 8; j++) {
            float p00 = exp2_fast(fmaf(sacc[j][0], SCALE, -mn0));
            float p01 = exp2_fast(fmaf(sacc[j][1], SCALE, -mn0));
            float p10 = exp2_fast(fmaf(sacc[j][2], SCALE, -mn1));
            float p11 = exp2_fast(fmaf(sacc[j][3], SCALE, -mn1));
            rs0 += p00 + p01;
            rs1 += p10 + p11;
            int s = j >> 1, hi = (j & 1) * 2;
            pf[s][hi]     = pack_h2(p00, p01);
            pf[s][hi + 1] = pack_h2(p10, p11);
        }
        rs0 += __shfl_xor_sync(0xffffffffu, rs0, 1);
        rs0 += __shfl_xor_sync(0xffffffffu, rs0, 2);
        rs1 += __shfl_xor_sync(0xffffffffu, rs1, 1);
        rs1 += __shfl_xor_sync(0xffffffffu, rs1, 2);
        l0 = l0 * c0 + rs0;
        l1 = l1 * c1 + rs1;
#pragma unroll
        for (int j = 0; j < 8; j++) {
            oacc[j][0] *= c0; oacc[j][1] *= c0;
            oacc[j][2] *= c1; oacc[j][3] *= c1;
        }

        // O += P @ V  (V row-major [m][dh]; B-fragments via ldmatrix.trans)
#pragma unroll
        for (int s = 0; s < 4; s++) {
            uint32_t bq[4][4];
#pragma unroll
            for (int jp = 0; jp < 4; jp++)
                ldmx4t(bq[jp], bufV + ((s * 16 + laneRowV) * 72 + jp * 16 + colV) * 2);
#pragma unroll
            for (int j = 0; j < 8; j++)
                mma_f16(oacc[j], pf[s], &bq[j >> 1][(j & 1) * 2]);
        }
    }

    float inv0 = 1.0f / l0, inv1 = 1.0f / l1;
    int row = n0 + wid * 16 + r_;
    __half* Ob = O + ((size_t)(b * SEQ_N + row)) * CDIM + h * DH;
#pragma unroll
    for (int j = 0; j < 8; j++) {
        int col = j * 8 + 2 * kq;
        *(uint32_t*)(Ob + col) = pack_h2(oacc[j][0] * inv0, oacc[j][1] * inv0);
        *(uint32_t*)(Ob + (size_t)8 * CDIM + col) = pack_h2(oacc[j][2] * inv1, oacc[j][3] * inv1);
    }
}

// ---------------------------------------------------------------------------
extern "C" void kernel_launch(void* const* d_in, const int* in_sizes, int n_in,
                              void* d_out, int out_size)
{
    const float* x   = (const float*)d_in[0];
    const float* ctx = (const float*)d_in[1];
    const float* Wq  = (const float*)d_in[2];
    const float* Wkv = (const float*)d_in[3];
    const float* Wo  = (const float*)d_in[4];
    float* out = (float*)d_out;

    __half *xh, *ch, *Qh, *KVh, *AOh, *WqTh, *WkvTh, *WoTh;
    cudaGetSymbolAddress((void**)&xh,    g_xh);
    cudaGetSymbolAddress((void**)&ch,    g_ch);
    cudaGetSymbolAddress((void**)&Qh,    g_Qh);
    cudaGetSymbolAddress((void**)&KVh,   g_KVh);
    cudaGetSymbolAddress((void**)&AOh,   g_AOh);
    cudaGetSymbolAddress((void**)&WqTh,  g_WqTh);
    cudaGetSymbolAddress((void**)&WkvTh, g_WkvTh);
    cudaGetSymbolAddress((void**)&WoTh,  g_WoTh);

    // fused prep: 1 conversion kernel + 1 weight-transpose kernel
    {
        int n1 = BATCH * SEQ_N * CDIM / 2;
        int n2 = BATCH * SEQ_M * CTXDIM / 2;
        f2h_all<<<(n1 + n2 + 255) / 256, 256>>>((const float2*)x, (uint32_t*)xh, n1,
                                                (const float2*)ctx, (uint32_t*)ch, n2);
        wtrans_all<<<dim3(2 * CDIM / 32, CDIM / 32, 3), dim3(32, 8)>>>(
            Wq, WqTh, Wkv, WkvTh, Wo, WoTh);
    }

    gemm_h<1><<<dim3(CDIM / 128, BATCH * SEQ_N / 128), 256>>>(
        xh, WqTh, Qh, BATCH * SEQ_N, CDIM, CDIM);
    gemm_h<1><<<dim3(2 * CDIM / 128, BATCH * SEQ_M / 128), 256>>>(
        ch, WkvTh, KVh, BATCH * SEQ_M, 2 * CDIM, CTXDIM);

    attn_h<<<dim3(BATCH * HEADS, SEQ_N / 64), 128>>>(Qh, KVh, AOh);

    gemm_h<0><<<dim3(CDIM / 128, BATCH * SEQ_N / 128), 256>>>(
        AOh, WoTh, out, BATCH * SEQ_N, CDIM, CDIM);
}

// round 9
// speedup vs baseline: 3.5540x; 1.0577x over previous
#include <cuda_runtime.h>
#include <cuda_fp16.h>
#include <cstdint>

// x: [2,2048,1024], ctx: [2,2048,768], Wq: [1024,1024], Wkv: [768,2048], Wo: [1024,1024]
#define BATCH 2
#define SEQ_N 2048
#define SEQ_M 2048
#define CDIM 1024
#define CTXDIM 768
#define HEADS 16
#define DH 64

// ---------------- device scratch (allocation-free rule) ----------------
__device__ __half g_xh [BATCH * SEQ_N * CDIM];
__device__ __half g_ch [BATCH * SEQ_M * CTXDIM];
__device__ __half g_Qh [BATCH * SEQ_N * CDIM];
__device__ __half g_KVh[BATCH * SEQ_M * 2 * CDIM];
__device__ __half g_AOh[BATCH * SEQ_N * CDIM];
__device__ __half g_WqTh [CDIM * CDIM];
__device__ __half g_WkvTh[2 * CDIM * CTXDIM];
__device__ __half g_WoTh [CDIM * CDIM];

// ---------------- helpers ----------------
__device__ __forceinline__ uint32_t smem_u32(const void* p) {
    uint32_t a;
    asm("{ .reg .u64 t; cvta.to.shared.u64 t, %1; cvt.u32.u64 %0, t; }" : "=r"(a) : "l"(p));
    return a;
}
__device__ __forceinline__ float exp2_fast(float x) {
    float r;
    asm("ex2.approx.ftz.f32 %0, %1;" : "=f"(r) : "f"(x));
    return r;
}
__device__ __forceinline__ uint32_t pack_h2(float lo, float hi) {
    uint32_t r;
    asm("cvt.rn.f16x2.f32 %0, %1, %2;" : "=r"(r) : "f"(hi), "f"(lo));
    return r;
}
__device__ __forceinline__ void cp16(uint32_t dst, const void* src) {
    asm volatile("cp.async.cg.shared.global [%0], [%1], 16;" :: "r"(dst), "l"(src));
}
#define CP_COMMIT() asm volatile("cp.async.commit_group;" ::: "memory")
#define CP_WAIT0()  asm volatile("cp.async.wait_group 0;" ::: "memory")
#define CP_WAIT1()  asm volatile("cp.async.wait_group 1;" ::: "memory")

__device__ __forceinline__ void ldmx4(uint32_t* r, uint32_t a) {
    asm volatile("ldmatrix.sync.aligned.m8n8.x4.shared.b16 {%0,%1,%2,%3}, [%4];"
        : "=r"(r[0]), "=r"(r[1]), "=r"(r[2]), "=r"(r[3]) : "r"(a));
}
__device__ __forceinline__ void ldmx4t(uint32_t* r, uint32_t a) {
    asm volatile("ldmatrix.sync.aligned.m8n8.x4.trans.shared.b16 {%0,%1,%2,%3}, [%4];"
        : "=r"(r[0]), "=r"(r[1]), "=r"(r[2]), "=r"(r[3]) : "r"(a));
}

// D += A@B (m16n8k16, fp16 in, fp32 acc)
__device__ __forceinline__ void mma_f16(float* d, const uint32_t* a, const uint32_t* b) {
    asm volatile(
        "mma.sync.aligned.m16n8k16.row.col.f32.f16.f16.f32 "
        "{%0,%1,%2,%3}, {%4,%5,%6,%7}, {%8,%9}, {%0,%1,%2,%3};"
        : "+f"(d[0]), "+f"(d[1]), "+f"(d[2]), "+f"(d[3])
        : "r"(a[0]), "r"(a[1]), "r"(a[2]), "r"(a[3]), "r"(b[0]), "r"(b[1]));
}

// ---------------- fused prep kernels ----------------
__global__ void f2h_all(const float2* __restrict__ x, uint32_t* __restrict__ xh, int n1,
                        const float2* __restrict__ c, uint32_t* __restrict__ ch, int n2) {
    int i = blockIdx.x * blockDim.x + threadIdx.x;
    if (i < n1) {
        float2 v = x[i];
        xh[i] = pack_h2(v.x, v.y);
    } else if (i < n1 + n2) {
        int j = i - n1;
        float2 v = c[j];
        ch[j] = pack_h2(v.x, v.y);
    }
}

__global__ void wtrans_all(const float* __restrict__ Wq,  __half* __restrict__ WqT,
                           const float* __restrict__ Wkv, __half* __restrict__ WkvT,
                           const float* __restrict__ Wo,  __half* __restrict__ WoT) {
    const float* in;
    __half* out;
    int K, N;
    if (blockIdx.z == 0)      { in = Wq;  out = WqT;  K = CDIM;   N = CDIM; }
    else if (blockIdx.z == 1) { in = Wkv; out = WkvT; K = CTXDIM; N = 2 * CDIM; }
    else                      { in = Wo;  out = WoT;  K = CDIM;   N = CDIM; }
    int n0 = blockIdx.x * 32, k0 = blockIdx.y * 32;
    if (n0 >= N || k0 >= K) return;
    __shared__ float t[32][33];
    int x = threadIdx.x, y = threadIdx.y;
#pragma unroll
    for (int i = 0; i < 32; i += 8)
        t[y + i][x] = in[(size_t)(k0 + y + i) * N + n0 + x];
    __syncthreads();
#pragma unroll
    for (int i = 0; i < 32; i += 8)
        out[(size_t)(n0 + y + i) * K + k0 + x] = __float2half(t[x][y + i]);
}

// ---------------- fp16 mma GEMM: C[M,N] = A[M,K] @ BT[N,K]^T ----------------
// 128x128 tile, BK=32, 3-stage cp.async, ONE __syncthreads per k-iter.
// 256 threads (8 warps: 4 in M x 2 in N; warp = 32x64). Pitch 40 halves.
#define GSTG 3
#define GSTG_H (128 * 40)              // halves per stage per array
#define GEMM_SMEM (GSTG * GSTG_H * 2 * 2)  // bytes (A + B)

template <int OUT_HALF>
__global__ __launch_bounds__(256) void gemm_h(const __half* __restrict__ A,
                                              const __half* __restrict__ BT,
                                              void* __restrict__ Cv,
                                              int M, int N, int K)
{
    extern __shared__ __half gsm[];
    __half* Asm = gsm;
    __half* Bsm = gsm + GSTG * GSTG_H;
    const int tid = threadIdx.x, lane = tid & 31, wid = tid >> 5;
    const int wm4 = wid & 3, wn = (wid >> 2) * 64;
    const int bx = blockIdx.x * 128, by = blockIdx.y * 128;
    const int r_ = lane >> 2, kq = lane & 3;
    const __half* Ag = A  + (size_t)by * K;
    const __half* Bg = BT + (size_t)bx * K;
    const uint32_t sA = smem_u32(Asm), sB = smem_u32(Bsm);

    const int laneRowA = (lane & 7) + ((lane >> 3) & 1) * 8;
    const int kA = (lane >> 4) * 8;
    const int laneRowB = (lane & 7) + (lane >> 4) * 8;
    const int kB = ((lane >> 3) & 1) * 8;

    float acc[2][8][4];
#pragma unroll
    for (int mi = 0; mi < 2; mi++)
#pragma unroll
        for (int j = 0; j < 8; j++)
#pragma unroll
            for (int q = 0; q < 4; q++) acc[mi][j][q] = 0.0f;

    auto copy_stage = [&](int buf, int k0) {
#pragma unroll
        for (int i = 0; i < 2; i++) {
            int id = tid + i * 256;
            int r = id >> 2, ch = id & 3;
            cp16(sA + buf * (GSTG_H * 2) + r * 80 + ch * 16, Ag + (size_t)r * K + k0 + ch * 8);
            cp16(sB + buf * (GSTG_H * 2) + r * 80 + ch * 16, Bg + (size_t)r * K + k0 + ch * 8);
        }
    };

    const int ns = K >> 5;
    // prologue: stages 0, 1
#pragma unroll
    for (int s = 0; s < GSTG - 1; s++) {
        copy_stage(s, s * 32);
        CP_COMMIT();
    }

    for (int st = 0; st < ns; st++) {
        const int buf = st % GSTG;
        asm volatile("cp.async.wait_group %0;" :: "n"(GSTG - 2) : "memory");
        __syncthreads();
        // issue copy for stage st+2 into buffer (st-1)%GSTG (consumed at iter st-1)
        if (st + GSTG - 1 < ns)
            copy_stage((st + GSTG - 1) % GSTG, (st + GSTG - 1) * 32);
        CP_COMMIT();   // always commit (possibly empty) to keep group accounting uniform

        const uint32_t bufA = sA + buf * (GSTG_H * 2);
        const uint32_t bufB = sB + buf * (GSTG_H * 2);
#pragma unroll
        for (int s = 0; s < 2; s++) {
            uint32_t af[2][4], bq[4][4];
#pragma unroll
            for (int mi = 0; mi < 2; mi++) {
                int row = wm4 * 32 + mi * 16 + laneRowA;
                ldmx4(af[mi], bufA + (row * 40 + s * 16 + kA) * 2);
            }
#pragma unroll
            for (int jp = 0; jp < 4; jp++) {
                int row = wn + jp * 16 + laneRowB;
                ldmx4(bq[jp], bufB + (row * 40 + s * 16 + kB) * 2);
            }
#pragma unroll
            for (int mi = 0; mi < 2; mi++)
#pragma unroll
                for (int j = 0; j < 8; j++)
                    mma_f16(acc[mi][j], af[mi], &bq[j >> 1][(j & 1) * 2]);
        }
    }

    if (OUT_HALF) {
        __half* C = (__half*)Cv;
#pragma unroll
        for (int mi = 0; mi < 2; mi++) {
            int r0 = by + wm4 * 32 + mi * 16 + r_;
#pragma unroll
            for (int j = 0; j < 8; j++) {
                int col = bx + wn + j * 8 + 2 * kq;
                *(uint32_t*)(C + (size_t)r0 * N + col) =
                    pack_h2(acc[mi][j][0], acc[mi][j][1]);
                *(uint32_t*)(C + (size_t)(r0 + 8) * N + col) =
                    pack_h2(acc[mi][j][2], acc[mi][j][3]);
            }
        }
    } else {
        float* C = (float*)Cv;
#pragma unroll
        for (int mi = 0; mi < 2; mi++) {
            int r0 = by + wm4 * 32 + mi * 16 + r_;
#pragma unroll
            for (int j = 0; j < 8; j++) {
                int col = bx + wn + j * 8 + 2 * kq;
                *(float2*)(C + (size_t)r0 * N + col) =
                    make_float2(acc[mi][j][0], acc[mi][j][1]);
                *(float2*)(C + (size_t)(r0 + 8) * N + col) =
                    make_float2(acc[mi][j][2], acc[mi][j][3]);
            }
        }
    }
}

// ---------------- FlashAttention-2, fp16 mma, single-sync pipeline ----------------
// Grid (B*H=32, N/64=32), 128 threads (4 warps; warp = 16 query rows).
__global__ __launch_bounds__(128) void attn_h(const __half* __restrict__ Q,
                                              const __half* __restrict__ KV,
                                              __half* __restrict__ O)
{
    __shared__ __half Qs[64 * 72];
    __shared__ __half Ks[2][64 * 72];
    __shared__ __half Vs[2][64 * 72];
    const int tid = threadIdx.x, lane = tid & 31, wid = tid >> 5;
    const int b = blockIdx.x >> 4, h = blockIdx.x & 15;
    const int n0 = blockIdx.y * 64;
    const int r_ = lane >> 2, kq = lane & 3;
    const uint32_t sQ = smem_u32(Qs), sK = smem_u32(Ks), sV = smem_u32(Vs);

    const int laneRowA = (lane & 7) + ((lane >> 3) & 1) * 8;
    const int kA = (lane >> 4) * 8;
    const int laneRowB = (lane & 7) + (lane >> 4) * 8;
    const int kB = ((lane >> 3) & 1) * 8;
    const int laneRowV = lane & 15;
    const int colV = (lane >> 4) * 8;

    const __half* Qg = Q  + ((size_t)(b * SEQ_N + n0)) * CDIM + h * DH;
    const __half* Kg = KV + (size_t)b * SEQ_M * (2 * CDIM) + h * DH;
    const __half* Vg = Kg + CDIM;

    auto copyKV = [&](int buf, int mt) {
#pragma unroll
        for (int i = 0; i < 4; i++) {
            int id = tid + i * 128, r = id >> 3, ch = id & 7;
            cp16(sK + buf * 9216 + r * 144 + ch * 16,
                 Kg + (size_t)(mt + r) * (2 * CDIM) + ch * 8);
            cp16(sV + buf * 9216 + r * 144 + ch * 16,
                 Vg + (size_t)(mt + r) * (2 * CDIM) + ch * 8);
        }
    };
    // prologue: Q + KV tile 0 in one group
#pragma unroll
    for (int i = 0; i < 4; i++) {
        int id = tid + i * 128, r = id >> 3, ch = id & 7;
        cp16(sQ + r * 144 + ch * 16, Qg + (size_t)r * CDIM + ch * 8);
    }
    copyKV(0, 0);
    CP_COMMIT();

    const float SCALE = 0.125f * 1.4426950408889634f;
    float m0r = -1e30f, m1r = -1e30f, l0 = 0.0f, l1 = 0.0f;
    float oacc[8][4];
#pragma unroll
    for (int j = 0; j < 8; j++)
#pragma unroll
        for (int q = 0; q < 4; q++) oacc[j][q] = 0.0f;
    uint32_t qf[4][4];

    const int nt = SEQ_M / 64;
    for (int t = 0; t < nt; t++) {
        const int buf = t & 1;
        CP_WAIT0();
        __syncthreads();
        if (t + 1 < nt) {
            copyKV(buf ^ 1, (t + 1) * 64);   // buffer consumed at t-1; safe after sync
            CP_COMMIT();
        }

        if (t == 0) {
            int row = wid * 16 + laneRowA;
#pragma unroll
            for (int s = 0; s < 4; s++)
                ldmx4(qf[s], sQ + (row * 72 + s * 16 + kA) * 2);
        }
        const uint32_t bufK = sK + buf * 9216;
        const uint32_t bufV = sV + buf * 9216;

        // S = Q @ K^T
        float sacc[8][4];
#pragma unroll
        for (int j = 0; j < 8; j++)
#pragma unroll
            for (int q = 0; q < 4; q++) sacc[j][q] = 0.0f;
#pragma unroll
        for (int s = 0; s < 4; s++) {
            uint32_t bq[4][4];
#pragma unroll
            for (int jp = 0; jp < 4; jp++) {
                int row = jp * 16 + laneRowB;
                ldmx4(bq[jp], bufK + (row * 72 + s * 16 + kB) * 2);
            }
#pragma unroll
            for (int j = 0; j < 8; j++)
                mma_f16(sacc[j], qf[s], &bq[j >> 1][(j & 1) * 2]);
        }

        // online softmax (exp2 domain)
        float rm0 = -1e30f, rm1 = -1e30f;
#pragma unroll
        for (int j = 0; j < 8; j++) {
            rm0 = fmaxf(rm0, fmaxf(sacc[j][0], sacc[j][1]));
            rm1 = fmaxf(rm1, fmaxf(sacc[j][2], sacc[j][3]));
        }
        rm0 = fmaxf(rm0, __shfl_xor_sync(0xffffffffu, rm0, 1));
        rm0 = fmaxf(rm0, __shfl_xor_sync(0xffffffffu, rm0, 2));
        rm1 = fmaxf(rm1, __shfl_xor_sync(0xffffffffu, rm1, 1));
        rm1 = fmaxf(rm1, __shfl_xor_sync(0xffffffffu, rm1, 2));
        rm0 *= SCALE; rm1 *= SCALE;
        float mn0 = fmaxf(m0r, rm0), mn1 = fmaxf(m1r, rm1);
        float c0 = exp2_fast(m0r - mn0), c1 = exp2_fast(m1r - mn1);
        m0r = mn0; m1r = mn1;

        float rs0 = 0.0f, rs1 = 0.0f;
        uint32_t pf[4][4];
#pragma unroll
        for (int j = 0; j < 8; j++) {
            float p00 = exp2_fast(fmaf(sacc[j][0], SCALE, -mn0));
            float p01 = exp2_fast(fmaf(sacc[j][1], SCALE, -mn0));
            float p10 = exp2_fast(fmaf(sacc[j][2], SCALE, -mn1));
            float p11 = exp2_fast(fmaf(sacc[j][3], SCALE, -mn1));
            rs0 += p00 + p01;
            rs1 += p10 + p11;
            int s = j >> 1, hi = (j & 1) * 2;
            pf[s][hi]     = pack_h2(p00, p01);
            pf[s][hi + 1] = pack_h2(p10, p11);
        }
        rs0 += __shfl_xor_sync(0xffffffffu, rs0, 1);
        rs0 += __shfl_xor_sync(0xffffffffu, rs0, 2);
        rs1 += __shfl_xor_sync(0xffffffffu, rs1, 1);
        rs1 += __shfl_xor_sync(0xffffffffu, rs1, 2);
        l0 = l0 * c0 + rs0;
        l1 = l1 * c1 + rs1;
#pragma unroll
        for (int j = 0; j < 8; j++) {
            oacc[j][0] *= c0; oacc[j][1] *= c0;
            oacc[j][2] *= c1; oacc[j][3] *= c1;
        }

        // O += P @ V  (V row-major; B-fragments via ldmatrix.trans)
#pragma unroll
        for (int s = 0; s < 4; s++) {
            uint32_t bq[4][4];
#pragma unroll
            for (int jp = 0; jp < 4; jp++)
                ldmx4t(bq[jp], bufV + ((s * 16 + laneRowV) * 72 + jp * 16 + colV) * 2);
#pragma unroll
            for (int j = 0; j < 8; j++)
                mma_f16(oacc[j], pf[s], &bq[j >> 1][(j & 1) * 2]);
        }
    }

    float inv0 = 1.0f / l0, inv1 = 1.0f / l1;
    int row = n0 + wid * 16 + r_;
    __half* Ob = O + ((size_t)(b * SEQ_N + row)) * CDIM + h * DH;
#pragma unroll
    for (int j = 0; j < 8; j++) {
        int col = j * 8 + 2 * kq;
        *(uint32_t*)(Ob + col) = pack_h2(oacc[j][0] * inv0, oacc[j][1] * inv0);
        *(uint32_t*)(Ob + (size_t)8 * CDIM + col) = pack_h2(oacc[j][2] * inv1, oacc[j][3] * inv1);
    }
}

// ---------------------------------------------------------------------------
extern "C" void kernel_launch(void* const* d_in, const int* in_sizes, int n_in,
                              void* d_out, int out_size)
{
    const float* x   = (const float*)d_in[0];
    const float* ctx = (const float*)d_in[1];
    const float* Wq  = (const float*)d_in[2];
    const float* Wkv = (const float*)d_in[3];
    const float* Wo  = (const float*)d_in[4];
    float* out = (float*)d_out;

    __half *xh, *ch, *Qh, *KVh, *AOh, *WqTh, *WkvTh, *WoTh;
    cudaGetSymbolAddress((void**)&xh,    g_xh);
    cudaGetSymbolAddress((void**)&ch,    g_ch);
    cudaGetSymbolAddress((void**)&Qh,    g_Qh);
    cudaGetSymbolAddress((void**)&KVh,   g_KVh);
    cudaGetSymbolAddress((void**)&AOh,   g_AOh);
    cudaGetSymbolAddress((void**)&WqTh,  g_WqTh);
    cudaGetSymbolAddress((void**)&WkvTh, g_WkvTh);
    cudaGetSymbolAddress((void**)&WoTh,  g_WoTh);

    {
        int n1 = BATCH * SEQ_N * CDIM / 2;
        int n2 = BATCH * SEQ_M * CTXDIM / 2;
        f2h_all<<<(n1 + n2 + 255) / 256, 256>>>((const float2*)x, (uint32_t*)xh, n1,
                                                (const float2*)ctx, (uint32_t*)ch, n2);
        wtrans_all<<<dim3(2 * CDIM / 32, CDIM / 32, 3), dim3(32, 8)>>>(
            Wq, WqTh, Wkv, WkvTh, Wo, WoTh);
    }

    cudaFuncSetAttribute(gemm_h<1>, cudaFuncAttributeMaxDynamicSharedMemorySize, GEMM_SMEM);
    cudaFuncSetAttribute(gemm_h<0>, cudaFuncAttributeMaxDynamicSharedMemorySize, GEMM_SMEM);

    gemm_h<1><<<dim3(CDIM / 128, BATCH * SEQ_N / 128), 256, GEMM_SMEM>>>(
        xh, WqTh, Qh, BATCH * SEQ_N, CDIM, CDIM);
    gemm_h<1><<<dim3(2 * CDIM / 128, BATCH * SEQ_M / 128), 256, GEMM_SMEM>>>(
        ch, WkvTh, KVh, BATCH * SEQ_M, 2 * CDIM, CTXDIM);

    attn_h<<<dim3(BATCH * HEADS, SEQ_N / 64), 128>>>(Qh, KVh, AOh);

    gemm_h<0><<<dim3(CDIM / 128, BATCH * SEQ_N / 128), 256, GEMM_SMEM>>>(
        AOh, WoTh, out, BATCH * SEQ_N, CDIM, CDIM);
}